// round 15
// baseline (speedup 1.0000x reference)
#include <cuda_runtime.h>
#include <math.h>

#define T_   8
#define NV   8192
#define EE   131072
#define HH   8
#define CC   100
#define DG   128
#define DHD  16
#define DAGG 384
#define DR   256
#define DD1  128
#define DD2  64

// ---------------- scratch layout (floats; ints aliased) ----------------
constexpr long OFF_H    = 0;                                   // [T*NV*DG]
constexpr long OFF_X    = OFF_H    + (long)T_*NV*DG;           // [T*NV*DG]
constexpr long OFF_SS   = OFF_X    + (long)T_*NV*DG;           // [T*NV*HH]
constexpr long OFF_SD   = OFF_SS   + (long)T_*NV*HH;
constexpr long OFF_NUM  = OFF_SD   + (long)T_*NV*HH;           // [T*CC*DG]
constexpr long OFF_CD   = OFF_NUM  + (long)T_*CC*DG;           // [T*CC]
constexpr long OFF_MES  = OFF_CD   + (long)T_*CC;              // [T*CC*DG]
constexpr long OFF_MAC  = OFF_MES  + (long)T_*CC*DG;           // [T*DG] (contiguous after MES)
constexpr long OFF_ALPH = OFF_MAC  + (long)T_*DG;              // [T*NV*4]
constexpr long OFF_ZME  = OFF_ALPH + (long)T_*NV*4;            // [(T*CC+T)*1024]
constexpr long OFF_ZX   = OFF_ZME  + (long)(T_*CC+T_)*1024;    // [T*NV*4*DR] (interleaved)
constexpr long OFF_HS   = OFF_ZX   + (long)T_*NV*4*DR;         // [NV*DR]
constexpr long OFF_HS2  = OFF_HS   + (long)NV*DR;              // [NV*DR]
constexpr long OFF_CS   = OFF_HS2  + (long)NV*DR;              // [NV*DR]
constexpr long OFF_ES1  = OFF_CS   + (long)NV*DR;              // [NV*2*DD1] packed e1|s1
constexpr long OFF_EMBN = OFF_ES1  + (long)NV*2*DD1;           // [NV*DD2]
constexpr long OFF_SC   = OFF_EMBN + (long)NV*DD2;             // [NV*DD2]
constexpr long OFF_SQ   = OFF_SC   + (long)NV*DD2;             // [NV]
constexpr long OFF_CNI  = OFF_SQ   + (long)NV;                 // [DD2]
constexpr long OFF_WXI  = OFF_CNI  + (long)DD2;                // [384*1024]
constexpr long OFF_WHI  = OFF_WXI  + (long)DAGG*4*DR;          // [256*1024]
constexpr long OFF_BI   = OFF_WHI  + (long)DR*4*DR;            // [1024]
constexpr long OFF_WC   = OFF_BI   + (long)4*DR;               // [DR*256]
constexpr long OFF_BC   = OFF_WC   + (long)DR*2*DD1;           // [256]
// CSR scratch (int-aliased)
constexpr long OFF_CNT  = OFF_BC   + (long)2*DD1;              // [T*NV] int
constexpr long OFF_ROW  = OFF_CNT  + (long)T_*NV;              // [T*NV] int
constexpr long OFF_CUR  = OFF_ROW  + (long)T_*NV;              // [T*NV] int
constexpr long OFF_SE   = OFF_CUR  + (long)T_*NV;              // [T*EE] int2
constexpr long TOTAL    = OFF_SE   + (long)T_*EE*2;

__device__ float g_buf[TOTAL];

// ---------------- helpers ----------------
__device__ __forceinline__ float fsig(float x){ return 1.f/(1.f+__expf(-x)); }
__device__ __forceinline__ float ftanh(float x){
    float t = __expf(-2.f*fabsf(x));
    float r = __fdividef(1.f - t, 1.f + t);
    return copysignf(r, x);
}
__device__ __forceinline__ float tanh_ap(float x){
    float r; asm("tanh.approx.f32 %0, %1;" : "=f"(r) : "f"(x)); return r;
}

__device__ __forceinline__ unsigned f2tf(float x){
    unsigned r; asm("cvt.rna.tf32.f32 %0, %1;" : "=r"(r) : "f"(x)); return r;
}
__device__ __forceinline__ float f2tf_f(float x){
    return __uint_as_float(f2tf(x));
}

__device__ __forceinline__ void mma_tf32(float* c, const unsigned* a, const unsigned* b){
    asm volatile("mma.sync.aligned.m16n8k8.row.col.f32.tf32.tf32.f32 "
        "{%0,%1,%2,%3}, {%4,%5,%6,%7}, {%8,%9}, {%0,%1,%2,%3};"
        : "+f"(c[0]),"+f"(c[1]),"+f"(c[2]),"+f"(c[3])
        : "r"(a[0]),"r"(a[1]),"r"(a[2]),"r"(a[3]), "r"(b[0]),"r"(b[1]));
}

__global__ void fill4(float4* p, long n4){
    long i = (long)blockIdx.x*blockDim.x + threadIdx.x;
    if (i < n4) p[i] = make_float4(0.f,0.f,0.f,0.f);
}

// interleave LSTM weights (+pre-round whi to tf32) + concat decoder L1 weights
__global__ void interleave_all(const float* __restrict__ wx, const float* __restrict__ wh,
                               const float* __restrict__ b, float* __restrict__ wxi,
                               float* __restrict__ whi, float* __restrict__ bi,
                               const float* __restrict__ eW0, const float* __restrict__ sW0,
                               const float* __restrict__ eb0, const float* __restrict__ sb0,
                               float* __restrict__ wc, float* __restrict__ bc)
{
    long idx = (long)blockIdx.x*blockDim.x + threadIdx.x;
    const long NWX = (long)DAGG*1024, NWH = (long)DR*1024;
    const long NWC = (long)DR*256;
    if (idx < NWX){
        long k = idx >> 10; int c = (int)(idx & 1023);
        wxi[idx] = wx[k*1024 + (c&3)*DR + (c>>2)];
    } else if (idx < NWX + NWH){
        long j = idx - NWX;
        long k = j >> 10; int c = (int)(j & 1023);
        whi[j] = f2tf_f(wh[k*1024 + (c&3)*DR + (c>>2)]);   // pre-rounded for cp.async gemm
    } else if (idx < NWX + NWH + 1024){
        int c = (int)(idx - NWX - NWH);
        bi[c] = b[(c&3)*DR + (c>>2)];
    } else if (idx < NWX + NWH + 1024 + NWC){
        long j = idx - NWX - NWH - 1024;
        long k = j >> 8; int c = (int)(j & 255);
        wc[j] = (c < DD1) ? eW0[k*DD1 + c] : sW0[k*DD1 + c - DD1];
    } else if (idx < NWX + NWH + 1024 + NWC + 256){
        int c = (int)(idx - NWX - NWH - 1024 - NWC);
        bc[c] = (c < DD1) ? eb0[c] : sb0[c - DD1];
    }
}

// ---------------- CSR build ----------------
__global__ void csr_hist(const int* __restrict__ ei, int* __restrict__ cnt){
    long idx = (long)blockIdx.x*blockDim.x + threadIdx.x;
    if (idx >= (long)T_*EE) return;
    int e = (int)(idx % EE), t = (int)(idx / EE);
    int dst = ei[(long)t*2*EE + EE + e];
    atomicAdd(&cnt[t*NV + dst], 1);
}

__global__ void csr_scan(const int* __restrict__ cnt, int* __restrict__ rowptr,
                         int* __restrict__ cursor)
{
    int t = blockIdx.x;          // T_ blocks
    int tid = threadIdx.x;       // 1024
    __shared__ int sm[1024];
    int base = t*NV + tid*8;
    int loc[8]; int s = 0;
    #pragma unroll
    for (int j=0;j<8;j++){ loc[j] = cnt[base+j]; s += loc[j]; }
    sm[tid] = s;
    __syncthreads();
    for (int off=1; off<1024; off<<=1){
        int v = (tid >= off) ? sm[tid-off] : 0;
        __syncthreads();
        sm[tid] += v;
        __syncthreads();
    }
    int off = (tid > 0) ? sm[tid-1] : 0;
    #pragma unroll
    for (int j=0;j<8;j++){
        rowptr[base+j] = off;
        cursor[base+j] = off;
        off += loc[j];
    }
}

__global__ void csr_scatter(const int* __restrict__ ei, int* __restrict__ cursor,
                            int2* __restrict__ se)
{
    long idx = (long)blockIdx.x*blockDim.x + threadIdx.x;
    if (idx >= (long)T_*EE) return;
    int e = (int)(idx % EE), t = (int)(idx / EE);
    int src = ei[(long)t*2*EE + e];
    int dst = ei[(long)t*2*EE + EE + e];
    int pos = atomicAdd(&cursor[t*NV + dst], 1);
    se[(long)t*EE + pos] = make_int2(src, e);
}

// ---------------- tf32 tensor-core GEMM ----------------
// act: 0 none, 1 tanh, 2 sigmoid, 3 split(col<128 tanh else sigmoid)
#define APAD 36
#define BPAD 136
__global__ void __launch_bounds__(256) gemm_tf32(
    const float* __restrict__ A, const float* __restrict__ B,
    const float* __restrict__ bias, float* __restrict__ Cm,
    int M, int Nn, int K, int accFlag, int act)
{
    __shared__ unsigned As[128*APAD];
    __shared__ unsigned Bs[32*BPAD];
    const int bx = blockIdx.x, by = blockIdx.y, tid = threadIdx.x;
    const int wid = tid >> 5, lane = tid & 31;
    const int wm = wid >> 1, wn = wid & 1;
    const int gID = lane >> 2, tig = lane & 3;

    float c[2][8][4];
    #pragma unroll
    for (int i=0;i<2;i++)
        #pragma unroll
        for (int j=0;j<8;j++)
            #pragma unroll
            for (int q=0;q<4;q++) c[i][j][q] = 0.f;

    const int am = tid >> 3;
    const int akq = (tid & 7) * 4;
    const int bk = tid >> 3;
    const int bn = (tid & 7) * 4;

    for (int k0 = 0; k0 < K; k0 += 32){
        #pragma unroll
        for (int r = 0; r < 4; r++){
            int m = am + r*32;
            float4 v = *(const float4*)(A + (long)(by*128 + m)*K + k0 + akq);
            unsigned* p = &As[m*APAD + akq];
            p[0]=f2tf(v.x); p[1]=f2tf(v.y); p[2]=f2tf(v.z); p[3]=f2tf(v.w);
        }
        #pragma unroll
        for (int q = 0; q < 4; q++){
            int n = bn + q*32;
            float4 v = *(const float4*)(B + (long)(k0 + bk)*Nn + bx*128 + n);
            unsigned* p = &Bs[bk*BPAD + n];
            p[0]=f2tf(v.x); p[1]=f2tf(v.y); p[2]=f2tf(v.z); p[3]=f2tf(v.w);
        }
        __syncthreads();

        #pragma unroll
        for (int ks = 0; ks < 4; ks++){
            const int k = ks*8;
            unsigned a[2][4];
            #pragma unroll
            for (int mf=0; mf<2; mf++){
                int bm = wm*32 + mf*16;
                a[mf][0] = As[(bm+gID  )*APAD + k + tig];
                a[mf][1] = As[(bm+gID+8)*APAD + k + tig];
                a[mf][2] = As[(bm+gID  )*APAD + k + tig + 4];
                a[mf][3] = As[(bm+gID+8)*APAD + k + tig + 4];
            }
            unsigned b[8][2];
            #pragma unroll
            for (int nf=0; nf<8; nf++){
                int bnn = wn*64 + nf*8;
                b[nf][0] = Bs[(k+tig  )*BPAD + bnn + gID];
                b[nf][1] = Bs[(k+tig+4)*BPAD + bnn + gID];
            }
            #pragma unroll
            for (int mf=0; mf<2; mf++)
                #pragma unroll
                for (int nf=0; nf<8; nf++)
                    mma_tf32(c[mf][nf], a[mf], b[nf]);
        }
        __syncthreads();
    }

    int actEff = act;
    if (act == 3) actEff = (bx == 0) ? 1 : 2;

    #pragma unroll
    for (int mf=0; mf<2; mf++){
        int row0 = by*128 + wm*32 + mf*16 + gID;
        #pragma unroll
        for (int nf=0; nf<8; nf++){
            int col = bx*128 + wn*64 + nf*8 + tig*2;
            #pragma unroll
            for (int half=0; half<2; half++){
                long row = row0 + half*8;
                float v0 = c[mf][nf][half*2+0];
                float v1 = c[mf][nf][half*2+1];
                if (bias){ v0 += bias[col]; v1 += bias[col+1]; }
                if (accFlag){
                    float2 o = *(float2*)(Cm + row*Nn + col);
                    v0 += o.x; v1 += o.y;
                }
                if (actEff == 1){ v0 = ftanh(v0); v1 = ftanh(v1); }
                else if (actEff == 2){ v0 = fsig(v0); v1 = fsig(v1); }
                *(float2*)(Cm + row*Nn + col) = make_float2(v0, v1);
            }
        }
    }
}

// ---------------- ZX gemm with hierarchical-combine epilogue ----------------
__global__ void __launch_bounds__(256) gemm_zx(
    const float* __restrict__ A, const float* __restrict__ B,
    const float* __restrict__ bias, const float4* __restrict__ alphas,
    const int* __restrict__ com, const float* __restrict__ zme,
    float* __restrict__ Cm)
{
    __shared__ unsigned As[128*APAD];
    __shared__ unsigned Bs[32*BPAD];
    const int Nn = 1024, K = DG;
    const int bx = blockIdx.x, by = blockIdx.y, tid = threadIdx.x;
    const int wid = tid >> 5, lane = tid & 31;
    const int wm = wid >> 1, wn = wid & 1;
    const int gID = lane >> 2, tig = lane & 3;

    float c[2][8][4];
    #pragma unroll
    for (int i=0;i<2;i++)
        #pragma unroll
        for (int j=0;j<8;j++)
            #pragma unroll
            for (int q=0;q<4;q++) c[i][j][q] = 0.f;

    const int am = tid >> 3;
    const int akq = (tid & 7) * 4;
    const int bk = tid >> 3;
    const int bn = (tid & 7) * 4;

    for (int k0 = 0; k0 < K; k0 += 32){
        #pragma unroll
        for (int r = 0; r < 4; r++){
            int m = am + r*32;
            float4 v = *(const float4*)(A + (long)(by*128 + m)*K + k0 + akq);
            unsigned* p = &As[m*APAD + akq];
            p[0]=f2tf(v.x); p[1]=f2tf(v.y); p[2]=f2tf(v.z); p[3]=f2tf(v.w);
        }
        #pragma unroll
        for (int q = 0; q < 4; q++){
            int n = bn + q*32;
            float4 v = *(const float4*)(B + (long)(k0 + bk)*Nn + bx*128 + n);
            unsigned* p = &Bs[bk*BPAD + n];
            p[0]=f2tf(v.x); p[1]=f2tf(v.y); p[2]=f2tf(v.z); p[3]=f2tf(v.w);
        }
        __syncthreads();

        #pragma unroll
        for (int ks = 0; ks < 4; ks++){
            const int k = ks*8;
            unsigned a[2][4];
            #pragma unroll
            for (int mf=0; mf<2; mf++){
                int bm = wm*32 + mf*16;
                a[mf][0] = As[(bm+gID  )*APAD + k + tig];
                a[mf][1] = As[(bm+gID+8)*APAD + k + tig];
                a[mf][2] = As[(bm+gID  )*APAD + k + tig + 4];
                a[mf][3] = As[(bm+gID+8)*APAD + k + tig + 4];
            }
            unsigned b[8][2];
            #pragma unroll
            for (int nf=0; nf<8; nf++){
                int bnn = wn*64 + nf*8;
                b[nf][0] = Bs[(k+tig  )*BPAD + bnn + gID];
                b[nf][1] = Bs[(k+tig+4)*BPAD + bnn + gID];
            }
            #pragma unroll
            for (int mf=0; mf<2; mf++)
                #pragma unroll
                for (int nf=0; nf<8; nf++)
                    mma_tf32(c[mf][nf], a[mf], b[nf]);
        }
        __syncthreads();
    }

    #pragma unroll
    for (int mf=0; mf<2; mf++){
        int row0 = by*128 + wm*32 + mf*16 + gID;
        #pragma unroll
        for (int nf=0; nf<8; nf++){
            int col = bx*128 + wn*64 + nf*8 + tig*2;
            #pragma unroll
            for (int half=0; half<2; half++){
                long row = row0 + half*8;
                float4 al = alphas[row];
                int t = (int)(row >> 13);             // NV = 8192
                int cc = com[row];
                const float* zm = zme + ((long)(t*CC + cc))*1024 + col;
                const float* za = zme + ((long)(T_*CC + t))*1024 + col;
                float v0 = al.x*c[mf][nf][half*2+0] + al.y*zm[0] + al.z*za[0] + bias[col];
                float v1 = al.x*c[mf][nf][half*2+1] + al.y*zm[1] + al.z*za[1] + bias[col+1];
                *(float2*)(Cm + row*(long)Nn + col) = make_float2(v0, v1);
            }
        }
    }
}

// ---------------- fused LSTM step: cp.async double-buffered ----------------
// A (h) and B (whi) are PRE-ROUNDED tf32 values in gmem -> no cvt needed.
#define GSTAGE (128*APAD + 32*BPAD)
#define GSMEM  (2*GSTAGE*4)
__global__ void __launch_bounds__(256) gemm_lstm(
    const float* __restrict__ A, const float* __restrict__ B,
    const float* __restrict__ zt, float* __restrict__ hout, float* __restrict__ cs)
{
    extern __shared__ unsigned sm2[];
    const int Nn = 4*DR, K = DR;
    const int bx = blockIdx.x, by = blockIdx.y, tid = threadIdx.x;
    const int wid = tid >> 5, lane = tid & 31;
    const int wm = wid >> 1, wn = wid & 1;
    const int gID = lane >> 2, tig = lane & 3;

    float c[2][8][4];
    #pragma unroll
    for (int i=0;i<2;i++)
        #pragma unroll
        for (int j=0;j<8;j++)
            #pragma unroll
            for (int q=0;q<4;q++) c[i][j][q] = 0.f;

    const int am = tid >> 3;
    const int akq = (tid & 7) * 4;
    const int bk = tid >> 3;
    const int bn = (tid & 7) * 4;

    auto issue = [&](int k0, int buf){
        unsigned* As = sm2 + buf*GSTAGE;
        unsigned* Bs = As + 128*APAD;
        #pragma unroll
        for (int r = 0; r < 4; r++){
            int m = am + r*32;
            const float* g = A + (long)(by*128 + m)*K + k0 + akq;
            unsigned sa = (unsigned)__cvta_generic_to_shared(&As[m*APAD + akq]);
            asm volatile("cp.async.cg.shared.global [%0], [%1], 16;\n" :: "r"(sa), "l"(g));
        }
        #pragma unroll
        for (int q = 0; q < 4; q++){
            int n = bn + q*32;
            const float* g = B + (long)(k0 + bk)*Nn + bx*128 + n;
            unsigned sa = (unsigned)__cvta_generic_to_shared(&Bs[bk*BPAD + n]);
            asm volatile("cp.async.cg.shared.global [%0], [%1], 16;\n" :: "r"(sa), "l"(g));
        }
        asm volatile("cp.async.commit_group;\n");
    };

    issue(0, 0);
    const int nIter = K >> 5;   // 8
    for (int it = 0; it < nIter; it++){
        if (it + 1 < nIter){
            issue((it+1) << 5, (it+1) & 1);
            asm volatile("cp.async.wait_group 1;\n");
        } else {
            asm volatile("cp.async.wait_group 0;\n");
        }
        __syncthreads();
        unsigned* As = sm2 + (it&1)*GSTAGE;
        unsigned* Bs = As + 128*APAD;
        #pragma unroll
        for (int ks = 0; ks < 4; ks++){
            const int k = ks*8;
            unsigned a[2][4];
            #pragma unroll
            for (int mf=0; mf<2; mf++){
                int bm = wm*32 + mf*16;
                a[mf][0] = As[(bm+gID  )*APAD + k + tig];
                a[mf][1] = As[(bm+gID+8)*APAD + k + tig];
                a[mf][2] = As[(bm+gID  )*APAD + k + tig + 4];
                a[mf][3] = As[(bm+gID+8)*APAD + k + tig + 4];
            }
            unsigned b[8][2];
            #pragma unroll
            for (int nf=0; nf<8; nf++){
                int bnn = wn*64 + nf*8;
                b[nf][0] = Bs[(k+tig  )*BPAD + bnn + gID];
                b[nf][1] = Bs[(k+tig+4)*BPAD + bnn + gID];
            }
            #pragma unroll
            for (int mf=0; mf<2; mf++)
                #pragma unroll
                for (int nf=0; nf<8; nf++)
                    mma_tf32(c[mf][nf], a[mf], b[nf]);
        }
        __syncthreads();
    }

    #pragma unroll
    for (int mf=0; mf<2; mf++){
        int row0 = by*128 + wm*32 + mf*16 + gID;
        #pragma unroll
        for (int nf=0; nf<8; nf++){
            int col = bx*128 + wn*64 + nf*8 + tig*2;
            #pragma unroll
            for (int half=0; half<2; half++){
                long row = row0 + half*8;
                float v0 = c[mf][nf][half*2+0];
                float v1 = c[mf][nf][half*2+1];
                float2 o = *(const float2*)(zt + row*(long)Nn + col);
                v0 += o.x; v1 += o.y;
                float p0 = __shfl_xor_sync(0xffffffffu, v0, 1);
                float p1 = __shfl_xor_sync(0xffffffffu, v1, 1);
                if (!(tig & 1)){
                    int u = col >> 2;
                    long ci = row*(long)DR + u;
                    float cold = cs[ci];
                    float cn = fsig(v1)*cold + fsig(v0)*ftanh(p0);
                    cs[ci] = cn;
                    hout[ci] = f2tf_f(fsig(p1)*ftanh(cn));   // pre-round h for next step
                }
            }
        }
    }
}

__global__ void lstm_gate0(const float* __restrict__ zt, float* __restrict__ hs,
                           float* __restrict__ cs)
{
    long idx = (long)blockIdx.x*blockDim.x + threadIdx.x;
    if (idx >= (long)NV*DR) return;
    long row = idx >> 8; int u = (int)(idx & 255);
    float4 z = *(const float4*)(zt + row*1024 + u*4);
    float cn = fsig(z.x)*ftanh(z.z);
    cs[idx] = cn;
    hs[idx] = f2tf_f(fsig(z.w)*ftanh(cn));   // pre-round h
}

// ---------------- small gemm + activation (lda-aware) ----------------
__global__ void small_gemm(const float* __restrict__ A, const float* __restrict__ B,
                           const float* __restrict__ bias, float* __restrict__ Cm,
                           int M, int Nn, int K, int lda, int act)
{
    long idx = (long)blockIdx.x*blockDim.x + threadIdx.x;
    if (idx >= (long)M*Nn) return;
    int col = (int)(idx % Nn);
    long row = idx / Nn;
    float acc = bias ? bias[col] : 0.f;
    const float* a = A + row*lda;
    #pragma unroll 8
    for (int k=0;k<K;k++) acc += a[k]*__ldg(&B[(long)k*Nn+col]);
    if (act==1) acc = ftanh(acc);
    else if (act==2) acc = fsig(acc);
    Cm[idx] = acc;
}

// ---------------- GAT ----------------
__global__ void gat_scores(const float* __restrict__ h, const float* __restrict__ asrc,
                           const float* __restrict__ adst, float* __restrict__ ss,
                           float* __restrict__ sd)
{
    int idx = blockIdx.x*blockDim.x + threadIdx.x;   // T*NV*HH
    if (idx >= T_*NV*HH) return;
    int hh = idx % HH;
    long node = idx / HH;
    const float* hp = h + node*DG + hh*DHD;
    float a = 0.f, b = 0.f;
    #pragma unroll
    for (int d=0; d<DHD; d++){
        float v = hp[d];
        a += v*asrc[hh*DHD+d];
        b += v*adst[hh*DHD+d];
    }
    ss[idx] = a; sd[idx] = b;
}

// CSR gather with INLINE softmax: warp per (t,dst). NO atomics, no esc array.
__global__ void edge_gather(const int* __restrict__ rowptr, const int* __restrict__ cnt,
                            const int2* __restrict__ se, const float* __restrict__ ew,
                            const float* __restrict__ ss, const float* __restrict__ sd,
                            const float* __restrict__ h, float* __restrict__ xout)
{
    long gtid = (long)blockIdx.x*blockDim.x + threadIdx.x;
    long w = gtid >> 5;
    int lane = (int)(gtid & 31);
    if (w >= (long)T_*NV) return;
    int t = (int)(w / NV);
    int start = rowptr[w];
    int len = cnt[w];
    int hh = lane >> 2;
    float sdh = sd[w*HH + hh];
    float den = 0.f;
    float4 acc = make_float4(0.f,0.f,0.f,0.f);
    const int2* sep = se + (long)t*EE + start;
    const float* ewT = ew + (long)t*EE;
    const float* ssT = ss + (long)t*NV*HH;
    const float* hT = h + (long)t*NV*DG;
    for (int i = 0; i < len; i++){
        int2 p = __ldg(&sep[i]);
        float s = __ldg(&ssT[(long)p.x*HH + hh]) + sdh;
        s = (s > 0.f) ? s : 0.2f*s;
        float a = __expf(s * __ldg(&ewT[p.y]));
        den += a;
        float4 hv = *(const float4*)(hT + (long)p.x*DG + lane*4);
        acc.x += a*hv.x; acc.y += a*hv.y; acc.z += a*hv.z; acc.w += a*hv.w;
    }
    float inv = __fdividef(1.f, den + 1e-16f);
    acc.x *= inv; acc.y *= inv; acc.z *= inv; acc.w *= inv;
    acc.x = (acc.x > 0.f) ? acc.x : expm1f(acc.x);
    acc.y = (acc.y > 0.f) ? acc.y : expm1f(acc.y);
    acc.z = (acc.z > 0.f) ? acc.z : expm1f(acc.z);
    acc.w = (acc.w > 0.f) ? acc.w : expm1f(acc.w);
    *(float4*)(xout + w*DG + lane*4) = acc;
}

// ---------------- fuse ----------------
__global__ void fuse_pool(const float* __restrict__ x, const int* __restrict__ com,
                          const float* __restrict__ w, float* __restrict__ num,
                          float* __restrict__ cd)
{
    long idx = (long)blockIdx.x*blockDim.x + threadIdx.x;   // T*NV*32
    if (idx >= (long)T_*NV*32) return;
    int d4 = (int)(idx & 31);
    long tn = idx >> 5;
    int t = (int)(tn / NV);
    int c = com[tn];
    float wv = w[tn];
    float4 v = *(const float4*)(x + tn*DG + d4*4);
    float4* np = (float4*)(num + ((long)t*CC+c)*DG + d4*4);
    atomicAdd(np, make_float4(wv*v.x, wv*v.y, wv*v.z, wv*v.w));
    if (d4 == 0) atomicAdd(&cd[(long)t*CC + c], wv);
}

__global__ void fuse_finalize(const float* __restrict__ num, const float* __restrict__ cd,
                              float* __restrict__ meso, float* __restrict__ mac)
{
    int t = blockIdx.x;
    int d = threadIdx.x;   // 128
    float macn = 0.f, ws = 0.f;
    for (int c=0;c<CC;c++){
        float nv = num[((long)t*CC+c)*DG + d];
        float dv = cd[(long)t*CC + c];
        meso[((long)t*CC+c)*DG + d] = nv/(dv + 1e-16f);
        macn += nv; ws += dv;
    }
    mac[(long)t*DG + d] = macn/(ws + 1e-16f);
}

// alphas only (no AGG materialization)
__global__ void fuse_alpha(const float* __restrict__ x, const int* __restrict__ com,
                           const float* __restrict__ meso, const float* __restrict__ mac,
                           float4* __restrict__ alphas)
{
    long gtid = (long)blockIdx.x*blockDim.x + threadIdx.x;
    long wid = gtid >> 5;
    int lane = (int)(gtid & 31);
    if (wid >= (long)T_*NV) return;
    long tn = wid;
    int t = (int)(tn / NV);
    int c = com[tn];
    float4 mi = *(const float4*)(x + tn*DG + lane*4);
    float4 me = *(const float4*)(meso + ((long)t*CC+c)*DG + lane*4);
    float4 ma = *(const float4*)(mac + (long)t*DG + lane*4);
    float s0 = mi.x+mi.y+mi.z+mi.w;
    float s1 = me.x+me.y+me.z+me.w;
    float s2 = ma.x+ma.y+ma.z+ma.w;
    #pragma unroll
    for (int o=16;o>0;o>>=1){
        s0 += __shfl_xor_sync(0xffffffffu, s0, o);
        s1 += __shfl_xor_sync(0xffffffffu, s1, o);
        s2 += __shfl_xor_sync(0xffffffffu, s2, o);
    }
    if (lane == 0){
        s0 *= (1.f/DG); s1 *= (1.f/DG); s2 *= (1.f/DG);
        s0 = (s0>0.f)?s0:0.2f*s0;
        s1 = (s1>0.f)?s1:0.2f*s1;
        s2 = (s2>0.f)?s2:0.2f*s2;
        float mx = fmaxf(s0, fmaxf(s1, s2));
        float e0 = __expf(s0-mx), e1 = __expf(s1-mx), e2 = __expf(s2-mx);
        float inv = __fdividef(1.f, e0+e1+e2);
        alphas[tn] = make_float4(e0*inv, e1*inv, e2*inv, 0.f);
    }
}

// ---------------- decoder normalization ----------------
__global__ void colnorm_k(const float* __restrict__ emb, float* __restrict__ cni){
    int col = blockIdx.x;   // 64
    __shared__ float red[256];
    float s = 0.f;
    for (int n = threadIdx.x; n < NV; n += 256){
        float v = emb[(long)n*DD2 + col];
        s += v*v;
    }
    red[threadIdx.x] = s;
    __syncthreads();
    for (int o=128;o>0;o>>=1){
        if (threadIdx.x < o) red[threadIdx.x] += red[threadIdx.x+o];
        __syncthreads();
    }
    if (threadIdx.x == 0) cni[col] = 1.f / fmaxf(sqrtf(red[0]), 1e-12f);
}

__global__ void norm_sq(const float* __restrict__ emb, const float* __restrict__ cni,
                        float* __restrict__ embn, float* __restrict__ sq)
{
    long gtid = (long)blockIdx.x*blockDim.x + threadIdx.x;
    long row = gtid >> 5;
    int lane = (int)(gtid & 31);
    if (row >= NV) return;
    float a = emb[row*DD2 + lane]      * cni[lane];
    float b = emb[row*DD2 + 32 + lane] * cni[32 + lane];
    embn[row*DD2 + lane] = a;
    embn[row*DD2 + 32 + lane] = b;
    float s = a*a + b*b;
    #pragma unroll
    for (int o=16;o>0;o>>=1) s += __shfl_xor_sync(0xffffffffu, s, o);
    if (lane == 0) sq[row] = s;
}

// ---------------- adjacency: dual tf32 gram + single-MUFU tanh epilogue ----------------
#define ALD 68
#define BLD 136
__global__ void __launch_bounds__(256) adj_tc(
    const float* __restrict__ embn, const float* __restrict__ scal,
    const float* __restrict__ sq, float* __restrict__ out)
{
    extern __shared__ unsigned smu[];
    unsigned* AE = smu;
    unsigned* AS = AE + 128*ALD;
    unsigned* BE = AS + 128*ALD;
    unsigned* BS = BE + 64*BLD;
    float* sqI = (float*)(BS + 64*BLD);
    float* sqJ = sqI + 128;

    const int bi = blockIdx.y, bj = blockIdx.x, tid = threadIdx.x;
    const int wid = tid >> 5, lane = tid & 31;
    const int wm = wid >> 1, wn = wid & 1;
    const int gID = lane >> 2, tig = lane & 3;

    for (int i = tid; i < 128*16; i += 256){
        int r = i >> 4, c4 = (i & 15) * 4;
        float4 v = *(const float4*)(embn + ((long)(bi*128+r))*DD2 + c4);
        unsigned* p = &AE[r*ALD + c4];
        p[0]=f2tf(v.x); p[1]=f2tf(v.y); p[2]=f2tf(v.z); p[3]=f2tf(v.w);
        v = *(const float4*)(scal + ((long)(bi*128+r))*DD2 + c4);
        p = &AS[r*ALD + c4];
        p[0]=f2tf(v.x); p[1]=f2tf(v.y); p[2]=f2tf(v.z); p[3]=f2tf(v.w);
    }
    for (int i = tid; i < 128*16; i += 256){
        int n = i & 127, c4 = (i >> 7) * 4;
        float4 v = *(const float4*)(embn + ((long)(bj*128+n))*DD2 + c4);
        BE[(c4+0)*BLD+n]=f2tf(v.x); BE[(c4+1)*BLD+n]=f2tf(v.y);
        BE[(c4+2)*BLD+n]=f2tf(v.z); BE[(c4+3)*BLD+n]=f2tf(v.w);
        v = *(const float4*)(scal + ((long)(bj*128+n))*DD2 + c4);
        BS[(c4+0)*BLD+n]=f2tf(v.x); BS[(c4+1)*BLD+n]=f2tf(v.y);
        BS[(c4+2)*BLD+n]=f2tf(v.z); BS[(c4+3)*BLD+n]=f2tf(v.w);
    }
    if (tid < 128){ sqI[tid] = sq[bi*128+tid]; sqJ[tid] = sq[bj*128+tid]; }
    __syncthreads();

    float cd[2][8][4], cs[2][8][4];
    #pragma unroll
    for (int i=0;i<2;i++)
        #pragma unroll
        for (int j=0;j<8;j++)
            #pragma unroll
            for (int q=0;q<4;q++){ cd[i][j][q]=0.f; cs[i][j][q]=0.f; }

    #pragma unroll
    for (int ks = 0; ks < 8; ks++){
        const int k = ks*8;
        unsigned aE[2][4], aS[2][4];
        #pragma unroll
        for (int mf=0; mf<2; mf++){
            int bm = wm*32 + mf*16;
            aE[mf][0] = AE[(bm+gID  )*ALD + k + tig];
            aE[mf][1] = AE[(bm+gID+8)*ALD + k + tig];
            aE[mf][2] = AE[(bm+gID  )*ALD + k + tig + 4];
            aE[mf][3] = AE[(bm+gID+8)*ALD + k + tig + 4];
            aS[mf][0] = AS[(bm+gID  )*ALD + k + tig];
            aS[mf][1] = AS[(bm+gID+8)*ALD + k + tig];
            aS[mf][2] = AS[(bm+gID  )*ALD + k + tig + 4];
            aS[mf][3] = AS[(bm+gID+8)*ALD + k + tig + 4];
        }
        unsigned bE[8][2], bS[8][2];
        #pragma unroll
        for (int nf=0; nf<8; nf++){
            int bnn = wn*64 + nf*8;
            bE[nf][0] = BE[(k+tig  )*BLD + bnn + gID];
            bE[nf][1] = BE[(k+tig+4)*BLD + bnn + gID];
            bS[nf][0] = BS[(k+tig  )*BLD + bnn + gID];
            bS[nf][1] = BS[(k+tig+4)*BLD + bnn + gID];
        }
        #pragma unroll
        for (int mf=0; mf<2; mf++)
            #pragma unroll
            for (int nf=0; nf<8; nf++){
                mma_tf32(cd[mf][nf], aE[mf], bE[nf]);
                mma_tf32(cs[mf][nf], aS[mf], bS[nf]);
            }
    }

    #pragma unroll
    for (int mf=0; mf<2; mf++){
        int rl0 = wm*32 + mf*16 + gID;
        #pragma unroll
        for (int nf=0; nf<8; nf++){
            int cl = wn*64 + nf*8 + tig*2;
            #pragma unroll
            for (int half=0; half<2; half++){
                int rl = rl0 + half*8;
                float sqi = sqI[rl];
                float d0 = sqi + sqJ[cl]   - 2.f*cd[mf][nf][half*2+0];
                float d1 = sqi + sqJ[cl+1] - 2.f*cd[mf][nf][half*2+1];
                float v0 = 1.f + tanh_ap(-d0*cs[mf][nf][half*2+0]);
                float v1 = 1.f + tanh_ap(-d1*cs[mf][nf][half*2+1]);
                *(float2*)(out + ((long)(bi*128+rl))*NV + bj*128 + cl) = make_float2(v0, v1);
            }
        }
    }
}

// ---------------- launch ----------------
static inline unsigned nb(long n, int b){ return (unsigned)((n + b - 1) / b); }

extern "C" void kernel_launch(void* const* d_in, const int* in_sizes, int n_in,
                              void* d_out, int out_size)
{
    (void)in_sizes; (void)n_in; (void)out_size;
    const int*   ei   = (const int*)  d_in[0];
    const float* ew   = (const float*)d_in[1];
    const float* feat = (const float*)d_in[2];
    const int*   com  = (const int*)  d_in[3];
    const float* nw   = (const float*)d_in[4];
    const float* gatW = (const float*)d_in[5];
    const float* asrc = (const float*)d_in[6];
    const float* adst = (const float*)d_in[7];
    const float* lWx  = (const float*)d_in[8];
    const float* lWh  = (const float*)d_in[9];
    const float* lb   = (const float*)d_in[10];
    const float* eW0  = (const float*)d_in[11];
    const float* eb0  = (const float*)d_in[12];
    const float* eW1  = (const float*)d_in[13];
    const float* eb1  = (const float*)d_in[14];
    const float* sW0  = (const float*)d_in[15];
    const float* sb0  = (const float*)d_in[16];
    const float* sW1  = (const float*)d_in[17];
    const float* sb1  = (const float*)d_in[18];
    float* out = (float*)d_out;

    float* buf = nullptr;
    cudaGetSymbolAddress((void**)&buf, g_buf);
    float* bH   = buf + OFF_H;
    float* bX   = buf + OFF_X;
    float* bSS  = buf + OFF_SS;
    float* bSD  = buf + OFF_SD;
    float* bNUM = buf + OFF_NUM;
    float* bCD  = buf + OFF_CD;
    float* bMES = buf + OFF_MES;
    float* bMAC = buf + OFF_MAC;
    float4* bAL = (float4*)(buf + OFF_ALPH);
    float* bZME = buf + OFF_ZME;
    float* bZX  = buf + OFF_ZX;
    float* bHS  = buf + OFF_HS;
    float* bHS2 = buf + OFF_HS2;
    float* bCS  = buf + OFF_CS;
    float* bES1 = buf + OFF_ES1;
    float* bEMBN= buf + OFF_EMBN;
    float* bSC  = buf + OFF_SC;
    float* bSQ  = buf + OFF_SQ;
    float* bCNI = buf + OFF_CNI;
    float* bWXI = buf + OFF_WXI;
    float* bWHI = buf + OFF_WHI;
    float* bBI  = buf + OFF_BI;
    float* bWC  = buf + OFF_WC;
    float* bBC  = buf + OFF_BC;
    int*  iCNT  = (int*) (buf + OFF_CNT);
    int*  iROW  = (int*) (buf + OFF_ROW);
    int*  iCUR  = (int*) (buf + OFF_CUR);
    int2* iSE   = (int2*)(buf + OFF_SE);
    float* bEMB = out + (long)NV*NV;   // emb written directly into output

    static const int adj_smem = (2*128*ALD + 2*64*BLD + 256) * (int)sizeof(unsigned);
    cudaFuncSetAttribute(adj_tc, cudaFuncAttributeMaxDynamicSharedMemorySize, adj_smem);
    cudaFuncSetAttribute(gemm_lstm, cudaFuncAttributeMaxDynamicSharedMemorySize, GSMEM);

    // -------- weight prep + CSR build --------
    interleave_all<<<nb((long)(DAGG+DR)*1024 + 1024 + (long)DR*256 + 256, 256), 256>>>(
        lWx, lWh, lb, bWXI, bWHI, bBI, eW0, sW0, eb0, sb0, bWC, bBC);
    fill4<<<nb((long)T_*NV/4, 256), 256>>>((float4*)iCNT, (long)T_*NV/4);
    csr_hist<<<nb((long)T_*EE, 256), 256>>>(ei, iCNT);
    csr_scan<<<T_, 1024>>>(iCNT, iROW, iCUR);
    csr_scatter<<<nb((long)T_*EE, 256), 256>>>(ei, iCUR, iSE);

    // -------- GAT layers (softmax fused into gather) --------
    const float* xin = feat;
    for (int l = 0; l < 2; l++){
        gemm_tf32<<<dim3(DG/128, (T_*NV)/128), 256>>>(
            xin, gatW + (long)l*DG*DG, nullptr, bH, T_*NV, DG, DG, 0, 0);
        gat_scores<<<nb((long)T_*NV*HH, 256), 256>>>(bH, asrc + l*HH*DHD, adst + l*HH*DHD,
                                                     bSS, bSD);
        edge_gather<<<nb((long)T_*NV*32, 256), 256>>>(iROW, iCNT, iSE, ew, bSS, bSD, bH, bX);
        xin = bX;
    }

    // -------- hierarchical fuse (alphas only; z-combine folded into gemm_zx) --------
    fill4<<<nb((long)T_*CC*(DG+1)/4 + 1, 256), 256>>>((float4*)bNUM, ((long)T_*CC*(DG+1)+3)/4);
    fuse_pool<<<nb((long)T_*NV*32, 256), 256>>>(bX, com, nw, bNUM, bCD);
    fuse_finalize<<<T_, 128>>>(bNUM, bCD, bMES, bMAC);
    fuse_alpha<<<nb((long)T_*NV*32, 256), 256>>>(bX, com, bMES, bMAC, bAL);

    // meso rows through Wx[128:256] (interleaved), mac rows through Wx[256:384]
    small_gemm<<<nb((long)T_*CC*1024, 256), 256>>>(
        bMES, bWXI + (long)DG*1024, nullptr, bZME, T_*CC, 1024, DG, DG, 0);
    small_gemm<<<nb((long)T_*1024, 256), 256>>>(
        bMAC, bWXI + (long)2*DG*1024, nullptr, bZME + (long)T_*CC*1024, T_, 1024, DG, DG, 0);

    // -------- LSTM: ZX via reduced gemm + combine epilogue; pipelined fused gates --------
    gemm_zx<<<dim3(8, (T_*NV)/128), 256>>>(bX, bWXI, bBI, bAL, com, bZME, bZX);
    lstm_gate0<<<nb((long)NV*DR, 256), 256>>>(bZX, bHS, bCS);
    float* hcur = bHS;
    float* hnxt = bHS2;
    for (int t = 1; t < T_; t++){
        gemm_lstm<<<dim3((4*DR)/128, NV/128), 256, GSMEM>>>(
            hcur, bWHI, bZX + (long)t*NV*4*DR, hnxt, bCS);
        float* tmp = hcur; hcur = hnxt; hnxt = tmp;
    }

    // -------- decoders (merged first layer: [tanh|sigmoid] split by N-block) --------
    gemm_tf32<<<dim3(2, NV/128), 256>>>(hcur, bWC, bBC, bES1, NV, 2*DD1, DR, 0, 3);
    small_gemm<<<nb((long)NV*DD2, 256), 256>>>(bES1,       eW1, eb1, bEMB, NV, DD2, DD1, 2*DD1, 1);
    small_gemm<<<nb((long)NV*DD2, 256), 256>>>(bES1 + DD1, sW1, sb1, bSC,  NV, DD2, DD1, 2*DD1, 2);

    colnorm_k<<<DD2, 256>>>(bEMB, bCNI);
    norm_sq<<<nb((long)NV*32, 256), 256>>>(bEMB, bCNI, bEMBN, bSQ);

    // -------- adjacency --------
    adj_tc<<<dim3(NV/128, NV/128), 256, adj_smem>>>(bEMBN, bSC, bSQ, out);
}

// round 16
// speedup vs baseline: 1.4288x; 1.4288x over previous
#include <cuda_runtime.h>
#include <math.h>

#define T_   8
#define NV   8192
#define EE   131072
#define HH   8
#define CC   100
#define DG   128
#define DHD  16
#define DAGG 384
#define DR   256
#define DD1  128
#define DD2  64

// ---------------- scratch layout (floats; ints aliased) ----------------
constexpr long OFF_H    = 0;                                   // [T*NV*DG]
constexpr long OFF_X    = OFF_H    + (long)T_*NV*DG;           // [T*NV*DG]
constexpr long OFF_SS   = OFF_X    + (long)T_*NV*DG;           // [T*NV*HH]
constexpr long OFF_SD   = OFF_SS   + (long)T_*NV*HH;
constexpr long OFF_NUM  = OFF_SD   + (long)T_*NV*HH;           // [T*CC*DG]
constexpr long OFF_CD   = OFF_NUM  + (long)T_*CC*DG;           // [T*CC]
constexpr long OFF_MES  = OFF_CD   + (long)T_*CC;              // [T*CC*DG]
constexpr long OFF_MAC  = OFF_MES  + (long)T_*CC*DG;           // [T*DG] (contiguous after MES)
constexpr long OFF_ALPH = OFF_MAC  + (long)T_*DG;              // [T*NV*4]
constexpr long OFF_ZME  = OFF_ALPH + (long)T_*NV*4;            // [(T*CC+T)*1024]
constexpr long OFF_ZX   = OFF_ZME  + (long)(T_*CC+T_)*1024;    // [T*NV*4*DR] (interleaved)
constexpr long OFF_HS   = OFF_ZX   + (long)T_*NV*4*DR;         // [NV*DR]
constexpr long OFF_HS2  = OFF_HS   + (long)NV*DR;              // [NV*DR]
constexpr long OFF_CS   = OFF_HS2  + (long)NV*DR;              // [NV*DR]
constexpr long OFF_ES1  = OFF_CS   + (long)NV*DR;              // [NV*2*DD1] packed e1|s1
constexpr long OFF_EMBN = OFF_ES1  + (long)NV*2*DD1;           // [NV*DD2]
constexpr long OFF_SC   = OFF_EMBN + (long)NV*DD2;             // [NV*DD2]
constexpr long OFF_SQ   = OFF_SC   + (long)NV*DD2;             // [NV]
constexpr long OFF_CNI  = OFF_SQ   + (long)NV;                 // [DD2]
constexpr long OFF_WXI  = OFF_CNI  + (long)DD2;                // [384*1024]
constexpr long OFF_WHI  = OFF_WXI  + (long)DAGG*4*DR;          // [256*1024]
constexpr long OFF_BI   = OFF_WHI  + (long)DR*4*DR;            // [1024]
constexpr long OFF_WC   = OFF_BI   + (long)4*DR;               // [DR*256]
constexpr long OFF_BC   = OFF_WC   + (long)DR*2*DD1;           // [256]
// CSR scratch (int-aliased)
constexpr long OFF_CNT  = OFF_BC   + (long)2*DD1;              // [T*NV] int
constexpr long OFF_ROW  = OFF_CNT  + (long)T_*NV;              // [T*NV] int
constexpr long OFF_CUR  = OFF_ROW  + (long)T_*NV;              // [T*NV] int
constexpr long OFF_SE   = OFF_CUR  + (long)T_*NV;              // [T*EE] int2
constexpr long TOTAL    = OFF_SE   + (long)T_*EE*2;

__device__ float g_buf[TOTAL];

// ---------------- helpers ----------------
__device__ __forceinline__ float fsig(float x){ return 1.f/(1.f+__expf(-x)); }
__device__ __forceinline__ float ftanh(float x){
    float t = __expf(-2.f*fabsf(x));
    float r = __fdividef(1.f - t, 1.f + t);
    return copysignf(r, x);
}
__device__ __forceinline__ float tanh_ap(float x){
    float r; asm("tanh.approx.f32 %0, %1;" : "=f"(r) : "f"(x)); return r;
}

__device__ __forceinline__ unsigned f2tf(float x){
    unsigned r; asm("cvt.rna.tf32.f32 %0, %1;" : "=r"(r) : "f"(x)); return r;
}
__device__ __forceinline__ float f2tf_f(float x){
    return __uint_as_float(f2tf(x));
}

__device__ __forceinline__ void mma_tf32(float* c, const unsigned* a, const unsigned* b){
    asm volatile("mma.sync.aligned.m16n8k8.row.col.f32.tf32.tf32.f32 "
        "{%0,%1,%2,%3}, {%4,%5,%6,%7}, {%8,%9}, {%0,%1,%2,%3};"
        : "+f"(c[0]),"+f"(c[1]),"+f"(c[2]),"+f"(c[3])
        : "r"(a[0]),"r"(a[1]),"r"(a[2]),"r"(a[3]), "r"(b[0]),"r"(b[1]));
}

__global__ void fill4(float4* p, long n4){
    long i = (long)blockIdx.x*blockDim.x + threadIdx.x;
    if (i < n4) p[i] = make_float4(0.f,0.f,0.f,0.f);
}

// interleave LSTM weights (+pre-round whi to tf32) + concat decoder L1 weights
__global__ void interleave_all(const float* __restrict__ wx, const float* __restrict__ wh,
                               const float* __restrict__ b, float* __restrict__ wxi,
                               float* __restrict__ whi, float* __restrict__ bi,
                               const float* __restrict__ eW0, const float* __restrict__ sW0,
                               const float* __restrict__ eb0, const float* __restrict__ sb0,
                               float* __restrict__ wc, float* __restrict__ bc)
{
    long idx = (long)blockIdx.x*blockDim.x + threadIdx.x;
    const long NWX = (long)DAGG*1024, NWH = (long)DR*1024;
    const long NWC = (long)DR*256;
    if (idx < NWX){
        long k = idx >> 10; int c = (int)(idx & 1023);
        wxi[idx] = wx[k*1024 + (c&3)*DR + (c>>2)];
    } else if (idx < NWX + NWH){
        long j = idx - NWX;
        long k = j >> 10; int c = (int)(j & 1023);
        whi[j] = f2tf_f(wh[k*1024 + (c&3)*DR + (c>>2)]);   // pre-rounded for cp.async gemm
    } else if (idx < NWX + NWH + 1024){
        int c = (int)(idx - NWX - NWH);
        bi[c] = b[(c&3)*DR + (c>>2)];
    } else if (idx < NWX + NWH + 1024 + NWC){
        long j = idx - NWX - NWH - 1024;
        long k = j >> 8; int c = (int)(j & 255);
        wc[j] = (c < DD1) ? eW0[k*DD1 + c] : sW0[k*DD1 + c - DD1];
    } else if (idx < NWX + NWH + 1024 + NWC + 256){
        int c = (int)(idx - NWX - NWH - 1024 - NWC);
        bc[c] = (c < DD1) ? eb0[c] : sb0[c - DD1];
    }
}

// ---------------- CSR build ----------------
__global__ void csr_hist(const int* __restrict__ ei, int* __restrict__ cnt){
    long idx = (long)blockIdx.x*blockDim.x + threadIdx.x;
    if (idx >= (long)T_*EE) return;
    int e = (int)(idx % EE), t = (int)(idx / EE);
    int dst = ei[(long)t*2*EE + EE + e];
    atomicAdd(&cnt[t*NV + dst], 1);
}

__global__ void csr_scan(const int* __restrict__ cnt, int* __restrict__ rowptr,
                         int* __restrict__ cursor)
{
    int t = blockIdx.x;          // T_ blocks
    int tid = threadIdx.x;       // 1024
    __shared__ int sm[1024];
    int base = t*NV + tid*8;
    int loc[8]; int s = 0;
    #pragma unroll
    for (int j=0;j<8;j++){ loc[j] = cnt[base+j]; s += loc[j]; }
    sm[tid] = s;
    __syncthreads();
    for (int off=1; off<1024; off<<=1){
        int v = (tid >= off) ? sm[tid-off] : 0;
        __syncthreads();
        sm[tid] += v;
        __syncthreads();
    }
    int off = (tid > 0) ? sm[tid-1] : 0;
    #pragma unroll
    for (int j=0;j<8;j++){
        rowptr[base+j] = off;
        cursor[base+j] = off;
        off += loc[j];
    }
}

__global__ void csr_scatter(const int* __restrict__ ei, int* __restrict__ cursor,
                            int2* __restrict__ se)
{
    long idx = (long)blockIdx.x*blockDim.x + threadIdx.x;
    if (idx >= (long)T_*EE) return;
    int e = (int)(idx % EE), t = (int)(idx / EE);
    int src = ei[(long)t*2*EE + e];
    int dst = ei[(long)t*2*EE + EE + e];
    int pos = atomicAdd(&cursor[t*NV + dst], 1);
    se[(long)t*EE + pos] = make_int2(src, e);
}

// ---------------- tf32 tensor-core GEMM ----------------
// act: 0 none, 1 tanh, 2 sigmoid, 3 split(col<128 tanh else sigmoid)
#define APAD 36
#define BPAD 136
__global__ void __launch_bounds__(256) gemm_tf32(
    const float* __restrict__ A, const float* __restrict__ B,
    const float* __restrict__ bias, float* __restrict__ Cm,
    int M, int Nn, int K, int accFlag, int act)
{
    __shared__ unsigned As[128*APAD];
    __shared__ unsigned Bs[32*BPAD];
    const int bx = blockIdx.x, by = blockIdx.y, tid = threadIdx.x;
    const int wid = tid >> 5, lane = tid & 31;
    const int wm = wid >> 1, wn = wid & 1;
    const int gID = lane >> 2, tig = lane & 3;

    float c[2][8][4];
    #pragma unroll
    for (int i=0;i<2;i++)
        #pragma unroll
        for (int j=0;j<8;j++)
            #pragma unroll
            for (int q=0;q<4;q++) c[i][j][q] = 0.f;

    const int am = tid >> 3;
    const int akq = (tid & 7) * 4;
    const int bk = tid >> 3;
    const int bn = (tid & 7) * 4;

    for (int k0 = 0; k0 < K; k0 += 32){
        #pragma unroll
        for (int r = 0; r < 4; r++){
            int m = am + r*32;
            float4 v = *(const float4*)(A + (long)(by*128 + m)*K + k0 + akq);
            unsigned* p = &As[m*APAD + akq];
            p[0]=f2tf(v.x); p[1]=f2tf(v.y); p[2]=f2tf(v.z); p[3]=f2tf(v.w);
        }
        #pragma unroll
        for (int q = 0; q < 4; q++){
            int n = bn + q*32;
            float4 v = *(const float4*)(B + (long)(k0 + bk)*Nn + bx*128 + n);
            unsigned* p = &Bs[bk*BPAD + n];
            p[0]=f2tf(v.x); p[1]=f2tf(v.y); p[2]=f2tf(v.z); p[3]=f2tf(v.w);
        }
        __syncthreads();

        #pragma unroll
        for (int ks = 0; ks < 4; ks++){
            const int k = ks*8;
            unsigned a[2][4];
            #pragma unroll
            for (int mf=0; mf<2; mf++){
                int bm = wm*32 + mf*16;
                a[mf][0] = As[(bm+gID  )*APAD + k + tig];
                a[mf][1] = As[(bm+gID+8)*APAD + k + tig];
                a[mf][2] = As[(bm+gID  )*APAD + k + tig + 4];
                a[mf][3] = As[(bm+gID+8)*APAD + k + tig + 4];
            }
            unsigned b[8][2];
            #pragma unroll
            for (int nf=0; nf<8; nf++){
                int bnn = wn*64 + nf*8;
                b[nf][0] = Bs[(k+tig  )*BPAD + bnn + gID];
                b[nf][1] = Bs[(k+tig+4)*BPAD + bnn + gID];
            }
            #pragma unroll
            for (int mf=0; mf<2; mf++)
                #pragma unroll
                for (int nf=0; nf<8; nf++)
                    mma_tf32(c[mf][nf], a[mf], b[nf]);
        }
        __syncthreads();
    }

    int actEff = act;
    if (act == 3) actEff = (bx == 0) ? 1 : 2;

    #pragma unroll
    for (int mf=0; mf<2; mf++){
        int row0 = by*128 + wm*32 + mf*16 + gID;
        #pragma unroll
        for (int nf=0; nf<8; nf++){
            int col = bx*128 + wn*64 + nf*8 + tig*2;
            #pragma unroll
            for (int half=0; half<2; half++){
                long row = row0 + half*8;
                float v0 = c[mf][nf][half*2+0];
                float v1 = c[mf][nf][half*2+1];
                if (bias){ v0 += bias[col]; v1 += bias[col+1]; }
                if (accFlag){
                    float2 o = *(float2*)(Cm + row*Nn + col);
                    v0 += o.x; v1 += o.y;
                }
                if (actEff == 1){ v0 = ftanh(v0); v1 = ftanh(v1); }
                else if (actEff == 2){ v0 = fsig(v0); v1 = fsig(v1); }
                *(float2*)(Cm + row*Nn + col) = make_float2(v0, v1);
            }
        }
    }
}

// ---------------- ZX gemm with hierarchical-combine epilogue ----------------
__global__ void __launch_bounds__(256) gemm_zx(
    const float* __restrict__ A, const float* __restrict__ B,
    const float* __restrict__ bias, const float4* __restrict__ alphas,
    const int* __restrict__ com, const float* __restrict__ zme,
    float* __restrict__ Cm)
{
    __shared__ unsigned As[128*APAD];
    __shared__ unsigned Bs[32*BPAD];
    const int Nn = 1024, K = DG;
    const int bx = blockIdx.x, by = blockIdx.y, tid = threadIdx.x;
    const int wid = tid >> 5, lane = tid & 31;
    const int wm = wid >> 1, wn = wid & 1;
    const int gID = lane >> 2, tig = lane & 3;

    float c[2][8][4];
    #pragma unroll
    for (int i=0;i<2;i++)
        #pragma unroll
        for (int j=0;j<8;j++)
            #pragma unroll
            for (int q=0;q<4;q++) c[i][j][q] = 0.f;

    const int am = tid >> 3;
    const int akq = (tid & 7) * 4;
    const int bk = tid >> 3;
    const int bn = (tid & 7) * 4;

    for (int k0 = 0; k0 < K; k0 += 32){
        #pragma unroll
        for (int r = 0; r < 4; r++){
            int m = am + r*32;
            float4 v = *(const float4*)(A + (long)(by*128 + m)*K + k0 + akq);
            unsigned* p = &As[m*APAD + akq];
            p[0]=f2tf(v.x); p[1]=f2tf(v.y); p[2]=f2tf(v.z); p[3]=f2tf(v.w);
        }
        #pragma unroll
        for (int q = 0; q < 4; q++){
            int n = bn + q*32;
            float4 v = *(const float4*)(B + (long)(k0 + bk)*Nn + bx*128 + n);
            unsigned* p = &Bs[bk*BPAD + n];
            p[0]=f2tf(v.x); p[1]=f2tf(v.y); p[2]=f2tf(v.z); p[3]=f2tf(v.w);
        }
        __syncthreads();

        #pragma unroll
        for (int ks = 0; ks < 4; ks++){
            const int k = ks*8;
            unsigned a[2][4];
            #pragma unroll
            for (int mf=0; mf<2; mf++){
                int bm = wm*32 + mf*16;
                a[mf][0] = As[(bm+gID  )*APAD + k + tig];
                a[mf][1] = As[(bm+gID+8)*APAD + k + tig];
                a[mf][2] = As[(bm+gID  )*APAD + k + tig + 4];
                a[mf][3] = As[(bm+gID+8)*APAD + k + tig + 4];
            }
            unsigned b[8][2];
            #pragma unroll
            for (int nf=0; nf<8; nf++){
                int bnn = wn*64 + nf*8;
                b[nf][0] = Bs[(k+tig  )*BPAD + bnn + gID];
                b[nf][1] = Bs[(k+tig+4)*BPAD + bnn + gID];
            }
            #pragma unroll
            for (int mf=0; mf<2; mf++)
                #pragma unroll
                for (int nf=0; nf<8; nf++)
                    mma_tf32(c[mf][nf], a[mf], b[nf]);
        }
        __syncthreads();
    }

    #pragma unroll
    for (int mf=0; mf<2; mf++){
        int row0 = by*128 + wm*32 + mf*16 + gID;
        #pragma unroll
        for (int nf=0; nf<8; nf++){
            int col = bx*128 + wn*64 + nf*8 + tig*2;
            #pragma unroll
            for (int half=0; half<2; half++){
                long row = row0 + half*8;
                float4 al = alphas[row];
                int t = (int)(row >> 13);             // NV = 8192
                int cc = com[row];
                const float* zm = zme + ((long)(t*CC + cc))*1024 + col;
                const float* za = zme + ((long)(T_*CC + t))*1024 + col;
                float v0 = al.x*c[mf][nf][half*2+0] + al.y*zm[0] + al.z*za[0] + bias[col];
                float v1 = al.x*c[mf][nf][half*2+1] + al.y*zm[1] + al.z*za[1] + bias[col+1];
                *(float2*)(Cm + row*(long)Nn + col) = make_float2(v0, v1);
            }
        }
    }
}

// ---------------- fused LSTM step: cp.async double-buffered ----------------
// A (h) and B (whi) are PRE-ROUNDED tf32 values in gmem -> no cvt needed.
#define GSTAGE (128*APAD + 32*BPAD)
#define GSMEM  (2*GSTAGE*4)
__global__ void __launch_bounds__(256) gemm_lstm(
    const float* __restrict__ A, const float* __restrict__ B,
    const float* __restrict__ zt, float* __restrict__ hout, float* __restrict__ cs)
{
    extern __shared__ unsigned sm2[];
    const int Nn = 4*DR, K = DR;
    const int bx = blockIdx.x, by = blockIdx.y, tid = threadIdx.x;
    const int wid = tid >> 5, lane = tid & 31;
    const int wm = wid >> 1, wn = wid & 1;
    const int gID = lane >> 2, tig = lane & 3;

    float c[2][8][4];
    #pragma unroll
    for (int i=0;i<2;i++)
        #pragma unroll
        for (int j=0;j<8;j++)
            #pragma unroll
            for (int q=0;q<4;q++) c[i][j][q] = 0.f;

    const int am = tid >> 3;
    const int akq = (tid & 7) * 4;
    const int bk = tid >> 3;
    const int bn = (tid & 7) * 4;

    auto issue = [&](int k0, int buf){
        unsigned* As = sm2 + buf*GSTAGE;
        unsigned* Bs = As + 128*APAD;
        #pragma unroll
        for (int r = 0; r < 4; r++){
            int m = am + r*32;
            const float* g = A + (long)(by*128 + m)*K + k0 + akq;
            unsigned sa = (unsigned)__cvta_generic_to_shared(&As[m*APAD + akq]);
            asm volatile("cp.async.cg.shared.global [%0], [%1], 16;\n" :: "r"(sa), "l"(g));
        }
        #pragma unroll
        for (int q = 0; q < 4; q++){
            int n = bn + q*32;
            const float* g = B + (long)(k0 + bk)*Nn + bx*128 + n;
            unsigned sa = (unsigned)__cvta_generic_to_shared(&Bs[bk*BPAD + n]);
            asm volatile("cp.async.cg.shared.global [%0], [%1], 16;\n" :: "r"(sa), "l"(g));
        }
        asm volatile("cp.async.commit_group;\n");
    };

    issue(0, 0);
    const int nIter = K >> 5;   // 8
    for (int it = 0; it < nIter; it++){
        if (it + 1 < nIter){
            issue((it+1) << 5, (it+1) & 1);
            asm volatile("cp.async.wait_group 1;\n");
        } else {
            asm volatile("cp.async.wait_group 0;\n");
        }
        __syncthreads();
        unsigned* As = sm2 + (it&1)*GSTAGE;
        unsigned* Bs = As + 128*APAD;
        #pragma unroll
        for (int ks = 0; ks < 4; ks++){
            const int k = ks*8;
            unsigned a[2][4];
            #pragma unroll
            for (int mf=0; mf<2; mf++){
                int bm = wm*32 + mf*16;
                a[mf][0] = As[(bm+gID  )*APAD + k + tig];
                a[mf][1] = As[(bm+gID+8)*APAD + k + tig];
                a[mf][2] = As[(bm+gID  )*APAD + k + tig + 4];
                a[mf][3] = As[(bm+gID+8)*APAD + k + tig + 4];
            }
            unsigned b[8][2];
            #pragma unroll
            for (int nf=0; nf<8; nf++){
                int bnn = wn*64 + nf*8;
                b[nf][0] = Bs[(k+tig  )*BPAD + bnn + gID];
                b[nf][1] = Bs[(k+tig+4)*BPAD + bnn + gID];
            }
            #pragma unroll
            for (int mf=0; mf<2; mf++)
                #pragma unroll
                for (int nf=0; nf<8; nf++)
                    mma_tf32(c[mf][nf], a[mf], b[nf]);
        }
        __syncthreads();
    }

    #pragma unroll
    for (int mf=0; mf<2; mf++){
        int row0 = by*128 + wm*32 + mf*16 + gID;
        #pragma unroll
        for (int nf=0; nf<8; nf++){
            int col = bx*128 + wn*64 + nf*8 + tig*2;
            #pragma unroll
            for (int half=0; half<2; half++){
                long row = row0 + half*8;
                float v0 = c[mf][nf][half*2+0];
                float v1 = c[mf][nf][half*2+1];
                float2 o = *(const float2*)(zt + row*(long)Nn + col);
                v0 += o.x; v1 += o.y;
                float p0 = __shfl_xor_sync(0xffffffffu, v0, 1);
                float p1 = __shfl_xor_sync(0xffffffffu, v1, 1);
                if (!(tig & 1)){
                    int u = col >> 2;
                    long ci = row*(long)DR + u;
                    float cold = cs[ci];
                    float cn = fsig(v1)*cold + fsig(v0)*ftanh(p0);
                    cs[ci] = cn;
                    hout[ci] = f2tf_f(fsig(p1)*ftanh(cn));   // pre-round h for next step
                }
            }
        }
    }
}

__global__ void lstm_gate0(const float* __restrict__ zt, float* __restrict__ hs,
                           float* __restrict__ cs)
{
    long idx = (long)blockIdx.x*blockDim.x + threadIdx.x;
    if (idx >= (long)NV*DR) return;
    long row = idx >> 8; int u = (int)(idx & 255);
    float4 z = *(const float4*)(zt + row*1024 + u*4);
    float cn = fsig(z.x)*ftanh(z.z);
    cs[idx] = cn;
    hs[idx] = f2tf_f(fsig(z.w)*ftanh(cn));   // pre-round h
}

// ---------------- small gemm + activation (lda-aware) ----------------
__global__ void small_gemm(const float* __restrict__ A, const float* __restrict__ B,
                           const float* __restrict__ bias, float* __restrict__ Cm,
                           int M, int Nn, int K, int lda, int act)
{
    long idx = (long)blockIdx.x*blockDim.x + threadIdx.x;
    if (idx >= (long)M*Nn) return;
    int col = (int)(idx % Nn);
    long row = idx / Nn;
    float acc = bias ? bias[col] : 0.f;
    const float* a = A + row*lda;
    #pragma unroll 8
    for (int k=0;k<K;k++) acc += a[k]*__ldg(&B[(long)k*Nn+col]);
    if (act==1) acc = ftanh(acc);
    else if (act==2) acc = fsig(acc);
    Cm[idx] = acc;
}

// ---------------- GAT ----------------
__global__ void gat_scores(const float* __restrict__ h, const float* __restrict__ asrc,
                           const float* __restrict__ adst, float* __restrict__ ss,
                           float* __restrict__ sd)
{
    int idx = blockIdx.x*blockDim.x + threadIdx.x;   // T*NV*HH
    if (idx >= T_*NV*HH) return;
    int hh = idx % HH;
    long node = idx / HH;
    const float* hp = h + node*DG + hh*DHD;
    float a = 0.f, b = 0.f;
    #pragma unroll
    for (int d=0; d<DHD; d++){
        float v = hp[d];
        a += v*asrc[hh*DHD+d];
        b += v*adst[hh*DHD+d];
    }
    ss[idx] = a; sd[idx] = b;
}

// CSR gather with INLINE softmax: warp per (t,dst). NO atomics, no esc array.
__global__ void edge_gather(const int* __restrict__ rowptr, const int* __restrict__ cnt,
                            const int2* __restrict__ se, const float* __restrict__ ew,
                            const float* __restrict__ ss, const float* __restrict__ sd,
                            const float* __restrict__ h, float* __restrict__ xout)
{
    long gtid = (long)blockIdx.x*blockDim.x + threadIdx.x;
    long w = gtid >> 5;
    int lane = (int)(gtid & 31);
    if (w >= (long)T_*NV) return;
    int t = (int)(w / NV);
    int start = rowptr[w];
    int len = cnt[w];
    int hh = lane >> 2;
    float sdh = sd[w*HH + hh];
    float den = 0.f;
    float4 acc = make_float4(0.f,0.f,0.f,0.f);
    const int2* sep = se + (long)t*EE + start;
    const float* ewT = ew + (long)t*EE;
    const float* ssT = ss + (long)t*NV*HH;
    const float* hT = h + (long)t*NV*DG;
    for (int i = 0; i < len; i++){
        int2 p = __ldg(&sep[i]);
        float s = __ldg(&ssT[(long)p.x*HH + hh]) + sdh;
        s = (s > 0.f) ? s : 0.2f*s;
        float a = __expf(s * __ldg(&ewT[p.y]));
        den += a;
        float4 hv = *(const float4*)(hT + (long)p.x*DG + lane*4);
        acc.x += a*hv.x; acc.y += a*hv.y; acc.z += a*hv.z; acc.w += a*hv.w;
    }
    float inv = __fdividef(1.f, den + 1e-16f);
    acc.x *= inv; acc.y *= inv; acc.z *= inv; acc.w *= inv;
    acc.x = (acc.x > 0.f) ? acc.x : expm1f(acc.x);
    acc.y = (acc.y > 0.f) ? acc.y : expm1f(acc.y);
    acc.z = (acc.z > 0.f) ? acc.z : expm1f(acc.z);
    acc.w = (acc.w > 0.f) ? acc.w : expm1f(acc.w);
    *(float4*)(xout + w*DG + lane*4) = acc;
}

// ---------------- fuse ----------------
__global__ void fuse_pool(const float* __restrict__ x, const int* __restrict__ com,
                          const float* __restrict__ w, float* __restrict__ num,
                          float* __restrict__ cd)
{
    long idx = (long)blockIdx.x*blockDim.x + threadIdx.x;   // T*NV*32
    if (idx >= (long)T_*NV*32) return;
    int d4 = (int)(idx & 31);
    long tn = idx >> 5;
    int t = (int)(tn / NV);
    int c = com[tn];
    float wv = w[tn];
    float4 v = *(const float4*)(x + tn*DG + d4*4);
    float4* np = (float4*)(num + ((long)t*CC+c)*DG + d4*4);
    atomicAdd(np, make_float4(wv*v.x, wv*v.y, wv*v.z, wv*v.w));
    if (d4 == 0) atomicAdd(&cd[(long)t*CC + c], wv);
}

__global__ void fuse_finalize(const float* __restrict__ num, const float* __restrict__ cd,
                              float* __restrict__ meso, float* __restrict__ mac)
{
    int t = blockIdx.x;
    int d = threadIdx.x;   // 128
    float macn = 0.f, ws = 0.f;
    for (int c=0;c<CC;c++){
        float nv = num[((long)t*CC+c)*DG + d];
        float dv = cd[(long)t*CC + c];
        meso[((long)t*CC+c)*DG + d] = nv/(dv + 1e-16f);
        macn += nv; ws += dv;
    }
    mac[(long)t*DG + d] = macn/(ws + 1e-16f);
}

// alphas only (no AGG materialization)
__global__ void fuse_alpha(const float* __restrict__ x, const int* __restrict__ com,
                           const float* __restrict__ meso, const float* __restrict__ mac,
                           float4* __restrict__ alphas)
{
    long gtid = (long)blockIdx.x*blockDim.x + threadIdx.x;
    long wid = gtid >> 5;
    int lane = (int)(gtid & 31);
    if (wid >= (long)T_*NV) return;
    long tn = wid;
    int t = (int)(tn / NV);
    int c = com[tn];
    float4 mi = *(const float4*)(x + tn*DG + lane*4);
    float4 me = *(const float4*)(meso + ((long)t*CC+c)*DG + lane*4);
    float4 ma = *(const float4*)(mac + (long)t*DG + lane*4);
    float s0 = mi.x+mi.y+mi.z+mi.w;
    float s1 = me.x+me.y+me.z+me.w;
    float s2 = ma.x+ma.y+ma.z+ma.w;
    #pragma unroll
    for (int o=16;o>0;o>>=1){
        s0 += __shfl_xor_sync(0xffffffffu, s0, o);
        s1 += __shfl_xor_sync(0xffffffffu, s1, o);
        s2 += __shfl_xor_sync(0xffffffffu, s2, o);
    }
    if (lane == 0){
        s0 *= (1.f/DG); s1 *= (1.f/DG); s2 *= (1.f/DG);
        s0 = (s0>0.f)?s0:0.2f*s0;
        s1 = (s1>0.f)?s1:0.2f*s1;
        s2 = (s2>0.f)?s2:0.2f*s2;
        float mx = fmaxf(s0, fmaxf(s1, s2));
        float e0 = __expf(s0-mx), e1 = __expf(s1-mx), e2 = __expf(s2-mx);
        float inv = __fdividef(1.f, e0+e1+e2);
        alphas[tn] = make_float4(e0*inv, e1*inv, e2*inv, 0.f);
    }
}

// ---------------- decoder normalization ----------------
__global__ void colnorm_k(const float* __restrict__ emb, float* __restrict__ cni){
    int col = blockIdx.x;   // 64
    __shared__ float red[256];
    float s = 0.f;
    for (int n = threadIdx.x; n < NV; n += 256){
        float v = emb[(long)n*DD2 + col];
        s += v*v;
    }
    red[threadIdx.x] = s;
    __syncthreads();
    for (int o=128;o>0;o>>=1){
        if (threadIdx.x < o) red[threadIdx.x] += red[threadIdx.x+o];
        __syncthreads();
    }
    if (threadIdx.x == 0) cni[col] = 1.f / fmaxf(sqrtf(red[0]), 1e-12f);
}

__global__ void norm_sq(const float* __restrict__ emb, const float* __restrict__ cni,
                        float* __restrict__ embn, float* __restrict__ sq)
{
    long gtid = (long)blockIdx.x*blockDim.x + threadIdx.x;
    long row = gtid >> 5;
    int lane = (int)(gtid & 31);
    if (row >= NV) return;
    float a = emb[row*DD2 + lane]      * cni[lane];
    float b = emb[row*DD2 + 32 + lane] * cni[32 + lane];
    embn[row*DD2 + lane] = a;
    embn[row*DD2 + 32 + lane] = b;
    float s = a*a + b*b;
    #pragma unroll
    for (int o=16;o>0;o>>=1) s += __shfl_xor_sync(0xffffffffu, s, o);
    if (lane == 0) sq[row] = s;
}

// ---------------- adjacency: dual tf32 gram + single-MUFU tanh epilogue ----------------
#define ALD 68
#define BLD 136
__global__ void __launch_bounds__(256) adj_tc(
    const float* __restrict__ embn, const float* __restrict__ scal,
    const float* __restrict__ sq, float* __restrict__ out)
{
    extern __shared__ unsigned smu[];
    unsigned* AE = smu;
    unsigned* AS = AE + 128*ALD;
    unsigned* BE = AS + 128*ALD;
    unsigned* BS = BE + 64*BLD;
    float* sqI = (float*)(BS + 64*BLD);
    float* sqJ = sqI + 128;

    const int bi = blockIdx.y, bj = blockIdx.x, tid = threadIdx.x;
    const int wid = tid >> 5, lane = tid & 31;
    const int wm = wid >> 1, wn = wid & 1;
    const int gID = lane >> 2, tig = lane & 3;

    for (int i = tid; i < 128*16; i += 256){
        int r = i >> 4, c4 = (i & 15) * 4;
        float4 v = *(const float4*)(embn + ((long)(bi*128+r))*DD2 + c4);
        unsigned* p = &AE[r*ALD + c4];
        p[0]=f2tf(v.x); p[1]=f2tf(v.y); p[2]=f2tf(v.z); p[3]=f2tf(v.w);
        v = *(const float4*)(scal + ((long)(bi*128+r))*DD2 + c4);
        p = &AS[r*ALD + c4];
        p[0]=f2tf(v.x); p[1]=f2tf(v.y); p[2]=f2tf(v.z); p[3]=f2tf(v.w);
    }
    for (int i = tid; i < 128*16; i += 256){
        int n = i & 127, c4 = (i >> 7) * 4;
        float4 v = *(const float4*)(embn + ((long)(bj*128+n))*DD2 + c4);
        BE[(c4+0)*BLD+n]=f2tf(v.x); BE[(c4+1)*BLD+n]=f2tf(v.y);
        BE[(c4+2)*BLD+n]=f2tf(v.z); BE[(c4+3)*BLD+n]=f2tf(v.w);
        v = *(const float4*)(scal + ((long)(bj*128+n))*DD2 + c4);
        BS[(c4+0)*BLD+n]=f2tf(v.x); BS[(c4+1)*BLD+n]=f2tf(v.y);
        BS[(c4+2)*BLD+n]=f2tf(v.z); BS[(c4+3)*BLD+n]=f2tf(v.w);
    }
    if (tid < 128){ sqI[tid] = sq[bi*128+tid]; sqJ[tid] = sq[bj*128+tid]; }
    __syncthreads();

    float cd[2][8][4], cs[2][8][4];
    #pragma unroll
    for (int i=0;i<2;i++)
        #pragma unroll
        for (int j=0;j<8;j++)
            #pragma unroll
            for (int q=0;q<4;q++){ cd[i][j][q]=0.f; cs[i][j][q]=0.f; }

    #pragma unroll
    for (int ks = 0; ks < 8; ks++){
        const int k = ks*8;
        unsigned aE[2][4], aS[2][4];
        #pragma unroll
        for (int mf=0; mf<2; mf++){
            int bm = wm*32 + mf*16;
            aE[mf][0] = AE[(bm+gID  )*ALD + k + tig];
            aE[mf][1] = AE[(bm+gID+8)*ALD + k + tig];
            aE[mf][2] = AE[(bm+gID  )*ALD + k + tig + 4];
            aE[mf][3] = AE[(bm+gID+8)*ALD + k + tig + 4];
            aS[mf][0] = AS[(bm+gID  )*ALD + k + tig];
            aS[mf][1] = AS[(bm+gID+8)*ALD + k + tig];
            aS[mf][2] = AS[(bm+gID  )*ALD + k + tig + 4];
            aS[mf][3] = AS[(bm+gID+8)*ALD + k + tig + 4];
        }
        unsigned bE[8][2], bS[8][2];
        #pragma unroll
        for (int nf=0; nf<8; nf++){
            int bnn = wn*64 + nf*8;
            bE[nf][0] = BE[(k+tig  )*BLD + bnn + gID];
            bE[nf][1] = BE[(k+tig+4)*BLD + bnn + gID];
            bS[nf][0] = BS[(k+tig  )*BLD + bnn + gID];
            bS[nf][1] = BS[(k+tig+4)*BLD + bnn + gID];
        }
        #pragma unroll
        for (int mf=0; mf<2; mf++)
            #pragma unroll
            for (int nf=0; nf<8; nf++){
                mma_tf32(cd[mf][nf], aE[mf], bE[nf]);
                mma_tf32(cs[mf][nf], aS[mf], bS[nf]);
            }
    }

    #pragma unroll
    for (int mf=0; mf<2; mf++){
        int rl0 = wm*32 + mf*16 + gID;
        #pragma unroll
        for (int nf=0; nf<8; nf++){
            int cl = wn*64 + nf*8 + tig*2;
            #pragma unroll
            for (int half=0; half<2; half++){
                int rl = rl0 + half*8;
                float sqi = sqI[rl];
                float d0 = sqi + sqJ[cl]   - 2.f*cd[mf][nf][half*2+0];
                float d1 = sqi + sqJ[cl+1] - 2.f*cd[mf][nf][half*2+1];
                float v0 = 1.f + tanh_ap(-d0*cs[mf][nf][half*2+0]);
                float v1 = 1.f + tanh_ap(-d1*cs[mf][nf][half*2+1]);
                *(float2*)(out + ((long)(bi*128+rl))*NV + bj*128 + cl) = make_float2(v0, v1);
            }
        }
    }
}

// ---------------- launch ----------------
static inline unsigned nb(long n, int b){ return (unsigned)((n + b - 1) / b); }

extern "C" void kernel_launch(void* const* d_in, const int* in_sizes, int n_in,
                              void* d_out, int out_size)
{
    (void)in_sizes; (void)n_in; (void)out_size;
    const int*   ei   = (const int*)  d_in[0];
    const float* ew   = (const float*)d_in[1];
    const float* feat = (const float*)d_in[2];
    const int*   com  = (const int*)  d_in[3];
    const float* nw   = (const float*)d_in[4];
    const float* gatW = (const float*)d_in[5];
    const float* asrc = (const float*)d_in[6];
    const float* adst = (const float*)d_in[7];
    const float* lWx  = (const float*)d_in[8];
    const float* lWh  = (const float*)d_in[9];
    const float* lb   = (const float*)d_in[10];
    const float* eW0  = (const float*)d_in[11];
    const float* eb0  = (const float*)d_in[12];
    const float* eW1  = (const float*)d_in[13];
    const float* eb1  = (const float*)d_in[14];
    const float* sW0  = (const float*)d_in[15];
    const float* sb0  = (const float*)d_in[16];
    const float* sW1  = (const float*)d_in[17];
    const float* sb1  = (const float*)d_in[18];
    float* out = (float*)d_out;

    float* buf = nullptr;
    cudaGetSymbolAddress((void**)&buf, g_buf);
    float* bH   = buf + OFF_H;
    float* bX   = buf + OFF_X;
    float* bSS  = buf + OFF_SS;
    float* bSD  = buf + OFF_SD;
    float* bNUM = buf + OFF_NUM;
    float* bCD  = buf + OFF_CD;
    float* bMES = buf + OFF_MES;
    float* bMAC = buf + OFF_MAC;
    float4* bAL = (float4*)(buf + OFF_ALPH);
    float* bZME = buf + OFF_ZME;
    float* bZX  = buf + OFF_ZX;
    float* bHS  = buf + OFF_HS;
    float* bHS2 = buf + OFF_HS2;
    float* bCS  = buf + OFF_CS;
    float* bES1 = buf + OFF_ES1;
    float* bEMBN= buf + OFF_EMBN;
    float* bSC  = buf + OFF_SC;
    float* bSQ  = buf + OFF_SQ;
    float* bCNI = buf + OFF_CNI;
    float* bWXI = buf + OFF_WXI;
    float* bWHI = buf + OFF_WHI;
    float* bBI  = buf + OFF_BI;
    float* bWC  = buf + OFF_WC;
    float* bBC  = buf + OFF_BC;
    int*  iCNT  = (int*) (buf + OFF_CNT);
    int*  iROW  = (int*) (buf + OFF_ROW);
    int*  iCUR  = (int*) (buf + OFF_CUR);
    int2* iSE   = (int2*)(buf + OFF_SE);
    float* bEMB = out + (long)NV*NV;   // emb written directly into output

    static const int adj_smem = (2*128*ALD + 2*64*BLD + 256) * (int)sizeof(unsigned);
    cudaFuncSetAttribute(adj_tc, cudaFuncAttributeMaxDynamicSharedMemorySize, adj_smem);
    cudaFuncSetAttribute(gemm_lstm, cudaFuncAttributeMaxDynamicSharedMemorySize, GSMEM);

    // -------- weight prep + CSR build --------
    interleave_all<<<nb((long)(DAGG+DR)*1024 + 1024 + (long)DR*256 + 256, 256), 256>>>(
        lWx, lWh, lb, bWXI, bWHI, bBI, eW0, sW0, eb0, sb0, bWC, bBC);
    fill4<<<nb((long)T_*NV/4, 256), 256>>>((float4*)iCNT, (long)T_*NV/4);
    csr_hist<<<nb((long)T_*EE, 256), 256>>>(ei, iCNT);
    csr_scan<<<T_, 1024>>>(iCNT, iROW, iCUR);
    csr_scatter<<<nb((long)T_*EE, 256), 256>>>(ei, iCUR, iSE);

    // -------- GAT layers (softmax fused into gather) --------
    const float* xin = feat;
    for (int l = 0; l < 2; l++){
        gemm_tf32<<<dim3(DG/128, (T_*NV)/128), 256>>>(
            xin, gatW + (long)l*DG*DG, nullptr, bH, T_*NV, DG, DG, 0, 0);
        gat_scores<<<nb((long)T_*NV*HH, 256), 256>>>(bH, asrc + l*HH*DHD, adst + l*HH*DHD,
                                                     bSS, bSD);
        edge_gather<<<nb((long)T_*NV*32, 256), 256>>>(iROW, iCNT, iSE, ew, bSS, bSD, bH, bX);
        xin = bX;
    }

    // -------- hierarchical fuse (alphas only; z-combine folded into gemm_zx) --------
    fill4<<<nb((long)T_*CC*(DG+1)/4 + 1, 256), 256>>>((float4*)bNUM, ((long)T_*CC*(DG+1)+3)/4);
    fuse_pool<<<nb((long)T_*NV*32, 256), 256>>>(bX, com, nw, bNUM, bCD);
    fuse_finalize<<<T_, 128>>>(bNUM, bCD, bMES, bMAC);
    fuse_alpha<<<nb((long)T_*NV*32, 256), 256>>>(bX, com, bMES, bMAC, bAL);

    // meso rows through Wx[128:256] (interleaved), mac rows through Wx[256:384]
    small_gemm<<<nb((long)T_*CC*1024, 256), 256>>>(
        bMES, bWXI + (long)DG*1024, nullptr, bZME, T_*CC, 1024, DG, DG, 0);
    small_gemm<<<nb((long)T_*1024, 256), 256>>>(
        bMAC, bWXI + (long)2*DG*1024, nullptr, bZME + (long)T_*CC*1024, T_, 1024, DG, DG, 0);

    // -------- LSTM: ZX via reduced gemm + combine epilogue; pipelined fused gates --------
    gemm_zx<<<dim3(8, (T_*NV)/128), 256>>>(bX, bWXI, bBI, bAL, com, bZME, bZX);
    lstm_gate0<<<nb((long)NV*DR, 256), 256>>>(bZX, bHS, bCS);
    float* hcur = bHS;
    float* hnxt = bHS2;
    for (int t = 1; t < T_; t++){
        gemm_lstm<<<dim3((4*DR)/128, NV/128), 256, GSMEM>>>(
            hcur, bWHI, bZX + (long)t*NV*4*DR, hnxt, bCS);
        float* tmp = hcur; hcur = hnxt; hnxt = tmp;
    }

    // -------- decoders (merged first layer: [tanh|sigmoid] split by N-block) --------
    gemm_tf32<<<dim3(2, NV/128), 256>>>(hcur, bWC, bBC, bES1, NV, 2*DD1, DR, 0, 3);
    small_gemm<<<nb((long)NV*DD2, 256), 256>>>(bES1,       eW1, eb1, bEMB, NV, DD2, DD1, 2*DD1, 1);
    small_gemm<<<nb((long)NV*DD2, 256), 256>>>(bES1 + DD1, sW1, sb1, bSC,  NV, DD2, DD1, 2*DD1, 2);

    colnorm_k<<<DD2, 256>>>(bEMB, bCNI);
    norm_sq<<<nb((long)NV*32, 256), 256>>>(bEMB, bCNI, bEMBN, bSQ);

    // -------- adjacency --------
    adj_tc<<<dim3(NV/128, NV/128), 256, adj_smem>>>(bEMBN, bSC, bSQ, out);
}

// round 17
// speedup vs baseline: 1.5263x; 1.0682x over previous
#include <cuda_runtime.h>
#include <math.h>

#define T_   8
#define NV   8192
#define EE   131072
#define HH   8
#define CC   100
#define DG   128
#define DHD  16
#define DAGG 384
#define DR   256
#define DD1  128
#define DD2  64

// ---------------- scratch layout (floats; ints aliased) ----------------
constexpr long OFF_H    = 0;                                   // [T*NV*DG]
constexpr long OFF_X    = OFF_H    + (long)T_*NV*DG;           // [T*NV*DG]
constexpr long OFF_SS   = OFF_X    + (long)T_*NV*DG;           // [T*NV*HH]
constexpr long OFF_SD   = OFF_SS   + (long)T_*NV*HH;
constexpr long OFF_NUM  = OFF_SD   + (long)T_*NV*HH;           // [T*CC*DG]
constexpr long OFF_CD   = OFF_NUM  + (long)T_*CC*DG;           // [T*CC]
constexpr long OFF_MES  = OFF_CD   + (long)T_*CC;              // [T*CC*DG]
constexpr long OFF_MAC  = OFF_MES  + (long)T_*CC*DG;           // [T*DG] (contiguous after MES)
constexpr long OFF_ALPH = OFF_MAC  + (long)T_*DG;              // [T*NV*4]
constexpr long OFF_ZME  = OFF_ALPH + (long)T_*NV*4;            // [(T*CC+T)*1024]
constexpr long OFF_ZX   = OFF_ZME  + (long)(T_*CC+T_)*1024;    // [T*NV*4*DR] (interleaved)
constexpr long OFF_HS   = OFF_ZX   + (long)T_*NV*4*DR;         // [NV*DR]
constexpr long OFF_HS2  = OFF_HS   + (long)NV*DR;              // [NV*DR]
constexpr long OFF_CS   = OFF_HS2  + (long)NV*DR;              // [NV*DR]
constexpr long OFF_ES1  = OFF_CS   + (long)NV*DR;              // [NV*2*DD1] packed e1|s1
constexpr long OFF_EMBN = OFF_ES1  + (long)NV*2*DD1;           // [NV*DD2]
constexpr long OFF_SC   = OFF_EMBN + (long)NV*DD2;             // [NV*DD2]
constexpr long OFF_SQ   = OFF_SC   + (long)NV*DD2;             // [NV]
constexpr long OFF_CNI  = OFF_SQ   + (long)NV;                 // [DD2]
constexpr long OFF_WXI  = OFF_CNI  + (long)DD2;                // [384*1024]
constexpr long OFF_WHI  = OFF_WXI  + (long)DAGG*4*DR;          // [256*1024]
constexpr long OFF_BI   = OFF_WHI  + (long)DR*4*DR;            // [1024]
constexpr long OFF_WC   = OFF_BI   + (long)4*DR;               // [DR*256]
constexpr long OFF_BC   = OFF_WC   + (long)DR*2*DD1;           // [256]
constexpr long OFF_GW   = OFF_BC   + (long)2*DD1;              // [2*DG*DG] rounded gatW
// CSR scratch (int-aliased)
constexpr long OFF_CNT  = OFF_GW   + (long)2*DG*DG;            // [T*NV] int
constexpr long OFF_ROW  = OFF_CNT  + (long)T_*NV;              // [T*NV] int
constexpr long OFF_CUR  = OFF_ROW  + (long)T_*NV;              // [T*NV] int
constexpr long OFF_SE   = OFF_CUR  + (long)T_*NV;              // [T*EE] int2
constexpr long TOTAL    = OFF_SE   + (long)T_*EE*2;

__device__ float g_buf[TOTAL];

// ---------------- helpers ----------------
__device__ __forceinline__ float fsig(float x){ return 1.f/(1.f+__expf(-x)); }
__device__ __forceinline__ float ftanh(float x){
    float t = __expf(-2.f*fabsf(x));
    float r = __fdividef(1.f - t, 1.f + t);
    return copysignf(r, x);
}
__device__ __forceinline__ float tanh_ap(float x){
    float r; asm("tanh.approx.f32 %0, %1;" : "=f"(r) : "f"(x)); return r;
}

__device__ __forceinline__ unsigned f2tf(float x){
    unsigned r; asm("cvt.rna.tf32.f32 %0, %1;" : "=r"(r) : "f"(x)); return r;
}
__device__ __forceinline__ float f2tf_f(float x){
    return __uint_as_float(f2tf(x));
}

__device__ __forceinline__ void mma_tf32(float* c, const unsigned* a, const unsigned* b){
    asm volatile("mma.sync.aligned.m16n8k8.row.col.f32.tf32.tf32.f32 "
        "{%0,%1,%2,%3}, {%4,%5,%6,%7}, {%8,%9}, {%0,%1,%2,%3};"
        : "+f"(c[0]),"+f"(c[1]),"+f"(c[2]),"+f"(c[3])
        : "r"(a[0]),"r"(a[1]),"r"(a[2]),"r"(a[3]), "r"(b[0]),"r"(b[1]));
}

__global__ void fill4(float4* p, long n4){
    long i = (long)blockIdx.x*blockDim.x + threadIdx.x;
    if (i < n4) p[i] = make_float4(0.f,0.f,0.f,0.f);
}

// elementwise tf32 pre-rounding (float4)
__global__ void round4(const float4* __restrict__ in, float4* __restrict__ o, long n4){
    long i = (long)blockIdx.x*blockDim.x + threadIdx.x;
    if (i >= n4) return;
    float4 v = in[i];
    o[i] = make_float4(f2tf_f(v.x), f2tf_f(v.y), f2tf_f(v.z), f2tf_f(v.w));
}

// interleave LSTM weights + concat decoder L1 weights + round gatW (ALL pre-rounded tf32)
__global__ void interleave_all(const float* __restrict__ wx, const float* __restrict__ wh,
                               const float* __restrict__ b, float* __restrict__ wxi,
                               float* __restrict__ whi, float* __restrict__ bi,
                               const float* __restrict__ eW0, const float* __restrict__ sW0,
                               const float* __restrict__ eb0, const float* __restrict__ sb0,
                               float* __restrict__ wc, float* __restrict__ bc,
                               const float* __restrict__ gatW, float* __restrict__ gw)
{
    long idx = (long)blockIdx.x*blockDim.x + threadIdx.x;
    const long NWX = (long)DAGG*1024, NWH = (long)DR*1024;
    const long NWC = (long)DR*256;
    const long NGW = (long)2*DG*DG;
    if (idx < NWX){
        long k = idx >> 10; int c = (int)(idx & 1023);
        wxi[idx] = f2tf_f(wx[k*1024 + (c&3)*DR + (c>>2)]);
    } else if (idx < NWX + NWH){
        long j = idx - NWX;
        long k = j >> 10; int c = (int)(j & 1023);
        whi[j] = f2tf_f(wh[k*1024 + (c&3)*DR + (c>>2)]);
    } else if (idx < NWX + NWH + 1024){
        int c = (int)(idx - NWX - NWH);
        bi[c] = b[(c&3)*DR + (c>>2)];
    } else if (idx < NWX + NWH + 1024 + NWC){
        long j = idx - NWX - NWH - 1024;
        long k = j >> 8; int c = (int)(j & 255);
        wc[j] = f2tf_f((c < DD1) ? eW0[k*DD1 + c] : sW0[k*DD1 + c - DD1]);
    } else if (idx < NWX + NWH + 1024 + NWC + 256){
        int c = (int)(idx - NWX - NWH - 1024 - NWC);
        bc[c] = (c < DD1) ? eb0[c] : sb0[c - DD1];
    } else if (idx < NWX + NWH + 1024 + NWC + 256 + NGW){
        long j = idx - NWX - NWH - 1024 - NWC - 256;
        gw[j] = f2tf_f(gatW[j]);
    }
}

// ---------------- CSR build ----------------
__global__ void csr_hist(const int* __restrict__ ei, int* __restrict__ cnt){
    long idx = (long)blockIdx.x*blockDim.x + threadIdx.x;
    if (idx >= (long)T_*EE) return;
    int e = (int)(idx % EE), t = (int)(idx / EE);
    int dst = ei[(long)t*2*EE + EE + e];
    atomicAdd(&cnt[t*NV + dst], 1);
}

__global__ void csr_scan(const int* __restrict__ cnt, int* __restrict__ rowptr,
                         int* __restrict__ cursor)
{
    int t = blockIdx.x;          // T_ blocks
    int tid = threadIdx.x;       // 1024
    __shared__ int sm[1024];
    int base = t*NV + tid*8;
    int loc[8]; int s = 0;
    #pragma unroll
    for (int j=0;j<8;j++){ loc[j] = cnt[base+j]; s += loc[j]; }
    sm[tid] = s;
    __syncthreads();
    for (int off=1; off<1024; off<<=1){
        int v = (tid >= off) ? sm[tid-off] : 0;
        __syncthreads();
        sm[tid] += v;
        __syncthreads();
    }
    int off = (tid > 0) ? sm[tid-1] : 0;
    #pragma unroll
    for (int j=0;j<8;j++){
        rowptr[base+j] = off;
        cursor[base+j] = off;
        off += loc[j];
    }
}

__global__ void csr_scatter(const int* __restrict__ ei, int* __restrict__ cursor,
                            int2* __restrict__ se)
{
    long idx = (long)blockIdx.x*blockDim.x + threadIdx.x;
    if (idx >= (long)T_*EE) return;
    int e = (int)(idx % EE), t = (int)(idx / EE);
    int src = ei[(long)t*2*EE + e];
    int dst = ei[(long)t*2*EE + EE + e];
    int pos = atomicAdd(&cursor[t*NV + dst], 1);
    se[(long)t*EE + pos] = make_int2(src, e);
}

// ---------------- pipelined tf32 gemm machinery (operands PRE-ROUNDED in gmem) ----------
#define APAD 36
#define BPAD 136
#define GSTAGE (128*APAD + 32*BPAD)
#define GSMEM  (2*GSTAGE*4)

#define GEMM_PIPE_BODY(Aptr, Bptr, Kval, Nval)                                           \
    const int am = tid >> 3;                                                             \
    const int akq = (tid & 7) * 4;                                                       \
    const int bk = tid >> 3;                                                             \
    const int bn = (tid & 7) * 4;                                                        \
    auto issue = [&](int k0, int buf){                                                   \
        unsigned* As_ = sm2 + buf*GSTAGE;                                                \
        unsigned* Bs_ = As_ + 128*APAD;                                                  \
        _Pragma("unroll")                                                                \
        for (int r = 0; r < 4; r++){                                                     \
            int m = am + r*32;                                                           \
            const float* g = Aptr + (long)(by*128 + m)*(Kval) + k0 + akq;                \
            unsigned sa = (unsigned)__cvta_generic_to_shared(&As_[m*APAD + akq]);        \
            asm volatile("cp.async.cg.shared.global [%0], [%1], 16;\n" :: "r"(sa), "l"(g)); \
        }                                                                                \
        _Pragma("unroll")                                                                \
        for (int q = 0; q < 4; q++){                                                     \
            int n = bn + q*32;                                                           \
            const float* g = Bptr + (long)(k0 + bk)*(Nval) + bx*128 + n;                 \
            unsigned sa = (unsigned)__cvta_generic_to_shared(&Bs_[bk*BPAD + n]);         \
            asm volatile("cp.async.cg.shared.global [%0], [%1], 16;\n" :: "r"(sa), "l"(g)); \
        }                                                                                \
        asm volatile("cp.async.commit_group;\n");                                       \
    };                                                                                   \
    issue(0, 0);                                                                         \
    const int nIter = (Kval) >> 5;                                                       \
    for (int it = 0; it < nIter; it++){                                                  \
        if (it + 1 < nIter){                                                             \
            issue((it+1) << 5, (it+1) & 1);                                              \
            asm volatile("cp.async.wait_group 1;\n");                                   \
        } else {                                                                         \
            asm volatile("cp.async.wait_group 0;\n");                                   \
        }                                                                                \
        __syncthreads();                                                                 \
        unsigned* As = sm2 + (it&1)*GSTAGE;                                              \
        unsigned* Bs = As + 128*APAD;                                                    \
        _Pragma("unroll")                                                                \
        for (int ks = 0; ks < 4; ks++){                                                  \
            const int k = ks*8;                                                          \
            unsigned a[2][4];                                                            \
            _Pragma("unroll")                                                            \
            for (int mf=0; mf<2; mf++){                                                  \
                int bm = wm*32 + mf*16;                                                  \
                a[mf][0] = As[(bm+gID  )*APAD + k + tig];                                \
                a[mf][1] = As[(bm+gID+8)*APAD + k + tig];                                \
                a[mf][2] = As[(bm+gID  )*APAD + k + tig + 4];                            \
                a[mf][3] = As[(bm+gID+8)*APAD + k + tig + 4];                            \
            }                                                                            \
            unsigned b[8][2];                                                            \
            _Pragma("unroll")                                                            \
            for (int nf=0; nf<8; nf++){                                                  \
                int bnn = wn*64 + nf*8;                                                  \
                b[nf][0] = Bs[(k+tig  )*BPAD + bnn + gID];                               \
                b[nf][1] = Bs[(k+tig+4)*BPAD + bnn + gID];                               \
            }                                                                            \
            _Pragma("unroll")                                                            \
            for (int mf=0; mf<2; mf++)                                                   \
                _Pragma("unroll")                                                        \
                for (int nf=0; nf<8; nf++)                                               \
                    mma_tf32(c[mf][nf], a[mf], b[nf]);                                   \
        }                                                                                \
        __syncthreads();                                                                 \
    }

// ---------------- generic pipelined gemm (+bias +act) ----------------
// act: 0 none, 1 tanh, 2 sigmoid, 3 split(bx==0 tanh else sigmoid)
__global__ void __launch_bounds__(256) gemm_tf32(
    const float* __restrict__ A, const float* __restrict__ B,
    const float* __restrict__ bias, float* __restrict__ Cm,
    int M, int Nn, int K, int act)
{
    extern __shared__ unsigned sm2[];
    const int bx = blockIdx.x, by = blockIdx.y, tid = threadIdx.x;
    const int wid = tid >> 5, lane = tid & 31;
    const int wm = wid >> 1, wn = wid & 1;
    const int gID = lane >> 2, tig = lane & 3;

    float c[2][8][4];
    #pragma unroll
    for (int i=0;i<2;i++)
        #pragma unroll
        for (int j=0;j<8;j++)
            #pragma unroll
            for (int q=0;q<4;q++) c[i][j][q] = 0.f;

    GEMM_PIPE_BODY(A, B, K, Nn)

    int actEff = act;
    if (act == 3) actEff = (bx == 0) ? 1 : 2;

    #pragma unroll
    for (int mf=0; mf<2; mf++){
        int row0 = by*128 + wm*32 + mf*16 + gID;
        #pragma unroll
        for (int nf=0; nf<8; nf++){
            int col = bx*128 + wn*64 + nf*8 + tig*2;
            #pragma unroll
            for (int half=0; half<2; half++){
                long row = row0 + half*8;
                float v0 = c[mf][nf][half*2+0];
                float v1 = c[mf][nf][half*2+1];
                if (bias){ v0 += bias[col]; v1 += bias[col+1]; }
                if (actEff == 1){ v0 = ftanh(v0); v1 = ftanh(v1); }
                else if (actEff == 2){ v0 = fsig(v0); v1 = fsig(v1); }
                *(float2*)(Cm + row*Nn + col) = make_float2(v0, v1);
            }
        }
    }
}

// ---------------- pipelined ZX gemm with hierarchical-combine epilogue ----------------
__global__ void __launch_bounds__(256) gemm_zx(
    const float* __restrict__ A, const float* __restrict__ B,
    const float* __restrict__ bias, const float4* __restrict__ alphas,
    const int* __restrict__ com, const float* __restrict__ zme,
    float* __restrict__ Cm)
{
    extern __shared__ unsigned sm2[];
    const int Nn = 1024, K = DG;
    const int bx = blockIdx.x, by = blockIdx.y, tid = threadIdx.x;
    const int wid = tid >> 5, lane = tid & 31;
    const int wm = wid >> 1, wn = wid & 1;
    const int gID = lane >> 2, tig = lane & 3;

    float c[2][8][4];
    #pragma unroll
    for (int i=0;i<2;i++)
        #pragma unroll
        for (int j=0;j<8;j++)
            #pragma unroll
            for (int q=0;q<4;q++) c[i][j][q] = 0.f;

    GEMM_PIPE_BODY(A, B, K, Nn)

    #pragma unroll
    for (int mf=0; mf<2; mf++){
        int row0 = by*128 + wm*32 + mf*16 + gID;
        #pragma unroll
        for (int nf=0; nf<8; nf++){
            int col = bx*128 + wn*64 + nf*8 + tig*2;
            #pragma unroll
            for (int half=0; half<2; half++){
                long row = row0 + half*8;
                float4 al = alphas[row];
                int t = (int)(row >> 13);             // NV = 8192
                int cc = com[row];
                const float* zm = zme + ((long)(t*CC + cc))*1024 + col;
                const float* za = zme + ((long)(T_*CC + t))*1024 + col;
                float v0 = al.x*c[mf][nf][half*2+0] + al.y*zm[0] + al.z*za[0] + bias[col];
                float v1 = al.x*c[mf][nf][half*2+1] + al.y*zm[1] + al.z*za[1] + bias[col+1];
                *(float2*)(Cm + row*(long)Nn + col) = make_float2(v0, v1);
            }
        }
    }
}

// ---------------- pipelined fused LSTM step ----------------
__global__ void __launch_bounds__(256) gemm_lstm(
    const float* __restrict__ A, const float* __restrict__ B,
    const float* __restrict__ zt, float* __restrict__ hout, float* __restrict__ cs)
{
    extern __shared__ unsigned sm2[];
    const int Nn = 4*DR, K = DR;
    const int bx = blockIdx.x, by = blockIdx.y, tid = threadIdx.x;
    const int wid = tid >> 5, lane = tid & 31;
    const int wm = wid >> 1, wn = wid & 1;
    const int gID = lane >> 2, tig = lane & 3;

    float c[2][8][4];
    #pragma unroll
    for (int i=0;i<2;i++)
        #pragma unroll
        for (int j=0;j<8;j++)
            #pragma unroll
            for (int q=0;q<4;q++) c[i][j][q] = 0.f;

    GEMM_PIPE_BODY(A, B, K, Nn)

    #pragma unroll
    for (int mf=0; mf<2; mf++){
        int row0 = by*128 + wm*32 + mf*16 + gID;
        #pragma unroll
        for (int nf=0; nf<8; nf++){
            int col = bx*128 + wn*64 + nf*8 + tig*2;
            #pragma unroll
            for (int half=0; half<2; half++){
                long row = row0 + half*8;
                float v0 = c[mf][nf][half*2+0];
                float v1 = c[mf][nf][half*2+1];
                float2 o = *(const float2*)(zt + row*(long)Nn + col);
                v0 += o.x; v1 += o.y;
                float p0 = __shfl_xor_sync(0xffffffffu, v0, 1);
                float p1 = __shfl_xor_sync(0xffffffffu, v1, 1);
                if (!(tig & 1)){
                    int u = col >> 2;
                    long ci = row*(long)DR + u;
                    float cold = cs[ci];
                    float cn = fsig(v1)*cold + fsig(v0)*ftanh(p0);
                    cs[ci] = cn;
                    hout[ci] = f2tf_f(fsig(p1)*ftanh(cn));   // pre-round h for next step
                }
            }
        }
    }
}

__global__ void lstm_gate0(const float* __restrict__ zt, float* __restrict__ hs,
                           float* __restrict__ cs)
{
    long idx = (long)blockIdx.x*blockDim.x + threadIdx.x;
    if (idx >= (long)NV*DR) return;
    long row = idx >> 8; int u = (int)(idx & 255);
    float4 z = *(const float4*)(zt + row*1024 + u*4);
    float cn = fsig(z.x)*ftanh(z.z);
    cs[idx] = cn;
    hs[idx] = f2tf_f(fsig(z.w)*ftanh(cn));   // pre-round h
}

// ---------------- small gemm + activation (lda-aware) ----------------
__global__ void small_gemm(const float* __restrict__ A, const float* __restrict__ B,
                           const float* __restrict__ bias, float* __restrict__ Cm,
                           int M, int Nn, int K, int lda, int act)
{
    long idx = (long)blockIdx.x*blockDim.x + threadIdx.x;
    if (idx >= (long)M*Nn) return;
    int col = (int)(idx % Nn);
    long row = idx / Nn;
    float acc = bias ? bias[col] : 0.f;
    const float* a = A + row*lda;
    #pragma unroll 8
    for (int k=0;k<K;k++) acc += a[k]*__ldg(&B[(long)k*Nn+col]);
    if (act==1) acc = ftanh(acc);
    else if (act==2) acc = fsig(acc);
    Cm[idx] = acc;
}

// ---------------- GAT ----------------
__global__ void gat_scores(const float* __restrict__ h, const float* __restrict__ asrc,
                           const float* __restrict__ adst, float* __restrict__ ss,
                           float* __restrict__ sd)
{
    int idx = blockIdx.x*blockDim.x + threadIdx.x;   // T*NV*HH
    if (idx >= T_*NV*HH) return;
    int hh = idx % HH;
    long node = idx / HH;
    const float* hp = h + node*DG + hh*DHD;
    float a = 0.f, b = 0.f;
    #pragma unroll
    for (int d=0; d<DHD; d++){
        float v = hp[d];
        a += v*asrc[hh*DHD+d];
        b += v*adst[hh*DHD+d];
    }
    ss[idx] = a; sd[idx] = b;
}

// CSR gather with INLINE softmax: warp per (t,dst). NO atomics. Output pre-rounded tf32.
__global__ void edge_gather(const int* __restrict__ rowptr, const int* __restrict__ cnt,
                            const int2* __restrict__ se, const float* __restrict__ ew,
                            const float* __restrict__ ss, const float* __restrict__ sd,
                            const float* __restrict__ h, float* __restrict__ xout)
{
    long gtid = (long)blockIdx.x*blockDim.x + threadIdx.x;
    long w = gtid >> 5;
    int lane = (int)(gtid & 31);
    if (w >= (long)T_*NV) return;
    int t = (int)(w / NV);
    int start = rowptr[w];
    int len = cnt[w];
    int hh = lane >> 2;
    float sdh = sd[w*HH + hh];
    float den = 0.f;
    float4 acc = make_float4(0.f,0.f,0.f,0.f);
    const int2* sep = se + (long)t*EE + start;
    const float* ewT = ew + (long)t*EE;
    const float* ssT = ss + (long)t*NV*HH;
    const float* hT = h + (long)t*NV*DG;
    for (int i = 0; i < len; i++){
        int2 p = __ldg(&sep[i]);
        float s = __ldg(&ssT[(long)p.x*HH + hh]) + sdh;
        s = (s > 0.f) ? s : 0.2f*s;
        float a = __expf(s * __ldg(&ewT[p.y]));
        den += a;
        float4 hv = *(const float4*)(hT + (long)p.x*DG + lane*4);
        acc.x += a*hv.x; acc.y += a*hv.y; acc.z += a*hv.z; acc.w += a*hv.w;
    }
    float inv = __fdividef(1.f, den + 1e-16f);
    acc.x *= inv; acc.y *= inv; acc.z *= inv; acc.w *= inv;
    acc.x = f2tf_f((acc.x > 0.f) ? acc.x : expm1f(acc.x));
    acc.y = f2tf_f((acc.y > 0.f) ? acc.y : expm1f(acc.y));
    acc.z = f2tf_f((acc.z > 0.f) ? acc.z : expm1f(acc.z));
    acc.w = f2tf_f((acc.w > 0.f) ? acc.w : expm1f(acc.w));
    *(float4*)(xout + w*DG + lane*4) = acc;
}

// ---------------- fuse ----------------
__global__ void fuse_pool(const float* __restrict__ x, const int* __restrict__ com,
                          const float* __restrict__ w, float* __restrict__ num,
                          float* __restrict__ cd)
{
    long idx = (long)blockIdx.x*blockDim.x + threadIdx.x;   // T*NV*32
    if (idx >= (long)T_*NV*32) return;
    int d4 = (int)(idx & 31);
    long tn = idx >> 5;
    int t = (int)(tn / NV);
    int c = com[tn];
    float wv = w[tn];
    float4 v = *(const float4*)(x + tn*DG + d4*4);
    float4* np = (float4*)(num + ((long)t*CC+c)*DG + d4*4);
    atomicAdd(np, make_float4(wv*v.x, wv*v.y, wv*v.z, wv*v.w));
    if (d4 == 0) atomicAdd(&cd[(long)t*CC + c], wv);
}

__global__ void fuse_finalize(const float* __restrict__ num, const float* __restrict__ cd,
                              float* __restrict__ meso, float* __restrict__ mac)
{
    int t = blockIdx.x;
    int d = threadIdx.x;   // 128
    float macn = 0.f, ws = 0.f;
    for (int c=0;c<CC;c++){
        float nv = num[((long)t*CC+c)*DG + d];
        float dv = cd[(long)t*CC + c];
        meso[((long)t*CC+c)*DG + d] = nv/(dv + 1e-16f);
        macn += nv; ws += dv;
    }
    mac[(long)t*DG + d] = macn/(ws + 1e-16f);
}

// alphas only (no AGG materialization)
__global__ void fuse_alpha(const float* __restrict__ x, const int* __restrict__ com,
                           const float* __restrict__ meso, const float* __restrict__ mac,
                           float4* __restrict__ alphas)
{
    long gtid = (long)blockIdx.x*blockDim.x + threadIdx.x;
    long wid = gtid >> 5;
    int lane = (int)(gtid & 31);
    if (wid >= (long)T_*NV) return;
    long tn = wid;
    int t = (int)(tn / NV);
    int c = com[tn];
    float4 mi = *(const float4*)(x + tn*DG + lane*4);
    float4 me = *(const float4*)(meso + ((long)t*CC+c)*DG + lane*4);
    float4 ma = *(const float4*)(mac + (long)t*DG + lane*4);
    float s0 = mi.x+mi.y+mi.z+mi.w;
    float s1 = me.x+me.y+me.z+me.w;
    float s2 = ma.x+ma.y+ma.z+ma.w;
    #pragma unroll
    for (int o=16;o>0;o>>=1){
        s0 += __shfl_xor_sync(0xffffffffu, s0, o);
        s1 += __shfl_xor_sync(0xffffffffu, s1, o);
        s2 += __shfl_xor_sync(0xffffffffu, s2, o);
    }
    if (lane == 0){
        s0 *= (1.f/DG); s1 *= (1.f/DG); s2 *= (1.f/DG);
        s0 = (s0>0.f)?s0:0.2f*s0;
        s1 = (s1>0.f)?s1:0.2f*s1;
        s2 = (s2>0.f)?s2:0.2f*s2;
        float mx = fmaxf(s0, fmaxf(s1, s2));
        float e0 = __expf(s0-mx), e1 = __expf(s1-mx), e2 = __expf(s2-mx);
        float inv = __fdividef(1.f, e0+e1+e2);
        alphas[tn] = make_float4(e0*inv, e1*inv, e2*inv, 0.f);
    }
}

// ---------------- decoder normalization ----------------
__global__ void colnorm_k(const float* __restrict__ emb, float* __restrict__ cni){
    int col = blockIdx.x;   // 64
    __shared__ float red[256];
    float s = 0.f;
    for (int n = threadIdx.x; n < NV; n += 256){
        float v = emb[(long)n*DD2 + col];
        s += v*v;
    }
    red[threadIdx.x] = s;
    __syncthreads();
    for (int o=128;o>0;o>>=1){
        if (threadIdx.x < o) red[threadIdx.x] += red[threadIdx.x+o];
        __syncthreads();
    }
    if (threadIdx.x == 0) cni[col] = 1.f / fmaxf(sqrtf(red[0]), 1e-12f);
}

__global__ void norm_sq(const float* __restrict__ emb, const float* __restrict__ cni,
                        float* __restrict__ embn, float* __restrict__ sq)
{
    long gtid = (long)blockIdx.x*blockDim.x + threadIdx.x;
    long row = gtid >> 5;
    int lane = (int)(gtid & 31);
    if (row >= NV) return;
    float a = emb[row*DD2 + lane]      * cni[lane];
    float b = emb[row*DD2 + 32 + lane] * cni[32 + lane];
    embn[row*DD2 + lane] = a;
    embn[row*DD2 + 32 + lane] = b;
    float s = a*a + b*b;
    #pragma unroll
    for (int o=16;o>0;o>>=1) s += __shfl_xor_sync(0xffffffffu, s, o);
    if (lane == 0) sq[row] = s;
}

// ---------------- adjacency: dual tf32 gram + single-MUFU tanh epilogue ----------------
#define ALD 68
#define BLD 136
__global__ void __launch_bounds__(256) adj_tc(
    const float* __restrict__ embn, const float* __restrict__ scal,
    const float* __restrict__ sq, float* __restrict__ out)
{
    extern __shared__ unsigned smu[];
    unsigned* AE = smu;
    unsigned* AS = AE + 128*ALD;
    unsigned* BE = AS + 128*ALD;
    unsigned* BS = BE + 64*BLD;
    float* sqI = (float*)(BS + 64*BLD);
    float* sqJ = sqI + 128;

    const int bi = blockIdx.y, bj = blockIdx.x, tid = threadIdx.x;
    const int wid = tid >> 5, lane = tid & 31;
    const int wm = wid >> 1, wn = wid & 1;
    const int gID = lane >> 2, tig = lane & 3;

    for (int i = tid; i < 128*16; i += 256){
        int r = i >> 4, c4 = (i & 15) * 4;
        float4 v = *(const float4*)(embn + ((long)(bi*128+r))*DD2 + c4);
        unsigned* p = &AE[r*ALD + c4];
        p[0]=f2tf(v.x); p[1]=f2tf(v.y); p[2]=f2tf(v.z); p[3]=f2tf(v.w);
        v = *(const float4*)(scal + ((long)(bi*128+r))*DD2 + c4);
        p = &AS[r*ALD + c4];
        p[0]=f2tf(v.x); p[1]=f2tf(v.y); p[2]=f2tf(v.z); p[3]=f2tf(v.w);
    }
    for (int i = tid; i < 128*16; i += 256){
        int n = i & 127, c4 = (i >> 7) * 4;
        float4 v = *(const float4*)(embn + ((long)(bj*128+n))*DD2 + c4);
        BE[(c4+0)*BLD+n]=f2tf(v.x); BE[(c4+1)*BLD+n]=f2tf(v.y);
        BE[(c4+2)*BLD+n]=f2tf(v.z); BE[(c4+3)*BLD+n]=f2tf(v.w);
        v = *(const float4*)(scal + ((long)(bj*128+n))*DD2 + c4);
        BS[(c4+0)*BLD+n]=f2tf(v.x); BS[(c4+1)*BLD+n]=f2tf(v.y);
        BS[(c4+2)*BLD+n]=f2tf(v.z); BS[(c4+3)*BLD+n]=f2tf(v.w);
    }
    if (tid < 128){ sqI[tid] = sq[bi*128+tid]; sqJ[tid] = sq[bj*128+tid]; }
    __syncthreads();

    float cd[2][8][4], cs[2][8][4];
    #pragma unroll
    for (int i=0;i<2;i++)
        #pragma unroll
        for (int j=0;j<8;j++)
            #pragma unroll
            for (int q=0;q<4;q++){ cd[i][j][q]=0.f; cs[i][j][q]=0.f; }

    #pragma unroll
    for (int ks = 0; ks < 8; ks++){
        const int k = ks*8;
        unsigned aE[2][4], aS[2][4];
        #pragma unroll
        for (int mf=0; mf<2; mf++){
            int bm = wm*32 + mf*16;
            aE[mf][0] = AE[(bm+gID  )*ALD + k + tig];
            aE[mf][1] = AE[(bm+gID+8)*ALD + k + tig];
            aE[mf][2] = AE[(bm+gID  )*ALD + k + tig + 4];
            aE[mf][3] = AE[(bm+gID+8)*ALD + k + tig + 4];
            aS[mf][0] = AS[(bm+gID  )*ALD + k + tig];
            aS[mf][1] = AS[(bm+gID+8)*ALD + k + tig];
            aS[mf][2] = AS[(bm+gID  )*ALD + k + tig + 4];
            aS[mf][3] = AS[(bm+gID+8)*ALD + k + tig + 4];
        }
        unsigned bE[8][2], bS[8][2];
        #pragma unroll
        for (int nf=0; nf<8; nf++){
            int bnn = wn*64 + nf*8;
            bE[nf][0] = BE[(k+tig  )*BLD + bnn + gID];
            bE[nf][1] = BE[(k+tig+4)*BLD + bnn + gID];
            bS[nf][0] = BS[(k+tig  )*BLD + bnn + gID];
            bS[nf][1] = BS[(k+tig+4)*BLD + bnn + gID];
        }
        #pragma unroll
        for (int mf=0; mf<2; mf++)
            #pragma unroll
            for (int nf=0; nf<8; nf++){
                mma_tf32(cd[mf][nf], aE[mf], bE[nf]);
                mma_tf32(cs[mf][nf], aS[mf], bS[nf]);
            }
    }

    #pragma unroll
    for (int mf=0; mf<2; mf++){
        int rl0 = wm*32 + mf*16 + gID;
        #pragma unroll
        for (int nf=0; nf<8; nf++){
            int cl = wn*64 + nf*8 + tig*2;
            #pragma unroll
            for (int half=0; half<2; half++){
                int rl = rl0 + half*8;
                float sqi = sqI[rl];
                float d0 = sqi + sqJ[cl]   - 2.f*cd[mf][nf][half*2+0];
                float d1 = sqi + sqJ[cl+1] - 2.f*cd[mf][nf][half*2+1];
                float v0 = 1.f + tanh_ap(-d0*cs[mf][nf][half*2+0]);
                float v1 = 1.f + tanh_ap(-d1*cs[mf][nf][half*2+1]);
                *(float2*)(out + ((long)(bi*128+rl))*NV + bj*128 + cl) = make_float2(v0, v1);
            }
        }
    }
}

// ---------------- launch ----------------
static inline unsigned nb(long n, int b){ return (unsigned)((n + b - 1) / b); }

extern "C" void kernel_launch(void* const* d_in, const int* in_sizes, int n_in,
                              void* d_out, int out_size)
{
    (void)in_sizes; (void)n_in; (void)out_size;
    const int*   ei   = (const int*)  d_in[0];
    const float* ew   = (const float*)d_in[1];
    const float* feat = (const float*)d_in[2];
    const int*   com  = (const int*)  d_in[3];
    const float* nw   = (const float*)d_in[4];
    const float* gatW = (const float*)d_in[5];
    const float* asrc = (const float*)d_in[6];
    const float* adst = (const float*)d_in[7];
    const float* lWx  = (const float*)d_in[8];
    const float* lWh  = (const float*)d_in[9];
    const float* lb   = (const float*)d_in[10];
    const float* eW0  = (const float*)d_in[11];
    const float* eb0  = (const float*)d_in[12];
    const float* eW1  = (const float*)d_in[13];
    const float* eb1  = (const float*)d_in[14];
    const float* sW0  = (const float*)d_in[15];
    const float* sb0  = (const float*)d_in[16];
    const float* sW1  = (const float*)d_in[17];
    const float* sb1  = (const float*)d_in[18];
    float* out = (float*)d_out;

    float* buf = nullptr;
    cudaGetSymbolAddress((void**)&buf, g_buf);
    float* bH   = buf + OFF_H;
    float* bX   = buf + OFF_X;
    float* bSS  = buf + OFF_SS;
    float* bSD  = buf + OFF_SD;
    float* bNUM = buf + OFF_NUM;
    float* bCD  = buf + OFF_CD;
    float* bMES = buf + OFF_MES;
    float* bMAC = buf + OFF_MAC;
    float4* bAL = (float4*)(buf + OFF_ALPH);
    float* bZME = buf + OFF_ZME;
    float* bZX  = buf + OFF_ZX;
    float* bHS  = buf + OFF_HS;
    float* bHS2 = buf + OFF_HS2;
    float* bCS  = buf + OFF_CS;
    float* bES1 = buf + OFF_ES1;
    float* bEMBN= buf + OFF_EMBN;
    float* bSC  = buf + OFF_SC;
    float* bSQ  = buf + OFF_SQ;
    float* bCNI = buf + OFF_CNI;
    float* bWXI = buf + OFF_WXI;
    float* bWHI = buf + OFF_WHI;
    float* bBI  = buf + OFF_BI;
    float* bWC  = buf + OFF_WC;
    float* bBC  = buf + OFF_BC;
    float* bGW  = buf + OFF_GW;
    int*  iCNT  = (int*) (buf + OFF_CNT);
    int*  iROW  = (int*) (buf + OFF_ROW);
    int*  iCUR  = (int*) (buf + OFF_CUR);
    int2* iSE   = (int2*)(buf + OFF_SE);
    float* bEMB = out + (long)NV*NV;   // emb written directly into output
    float* bFR  = bZX;                 // rounded feat (ZX region is free until LSTM)

    static const int adj_smem = (2*128*ALD + 2*64*BLD + 256) * (int)sizeof(unsigned);
    cudaFuncSetAttribute(adj_tc, cudaFuncAttributeMaxDynamicSharedMemorySize, adj_smem);
    cudaFuncSetAttribute(gemm_lstm, cudaFuncAttributeMaxDynamicSharedMemorySize, GSMEM);
    cudaFuncSetAttribute(gemm_tf32, cudaFuncAttributeMaxDynamicSharedMemorySize, GSMEM);
    cudaFuncSetAttribute(gemm_zx, cudaFuncAttributeMaxDynamicSharedMemorySize, GSMEM);

    // -------- weight prep + feat rounding + CSR build --------
    interleave_all<<<nb((long)(DAGG+DR)*1024 + 1024 + (long)DR*256 + 256 + (long)2*DG*DG, 256), 256>>>(
        lWx, lWh, lb, bWXI, bWHI, bBI, eW0, sW0, eb0, sb0, bWC, bBC, gatW, bGW);
    round4<<<nb((long)T_*NV*DG/4, 256), 256>>>((const float4*)feat, (float4*)bFR,
                                               (long)T_*NV*DG/4);
    fill4<<<nb((long)T_*NV/4, 256), 256>>>((float4*)iCNT, (long)T_*NV/4);
    csr_hist<<<nb((long)T_*EE, 256), 256>>>(ei, iCNT);
    csr_scan<<<T_, 1024>>>(iCNT, iROW, iCUR);
    csr_scatter<<<nb((long)T_*EE, 256), 256>>>(ei, iCUR, iSE);

    // -------- GAT layers (softmax fused into gather; pipelined gemms) --------
    const float* xin = bFR;
    for (int l = 0; l < 2; l++){
        gemm_tf32<<<dim3(DG/128, (T_*NV)/128), 256, GSMEM>>>(
            xin, bGW + (long)l*DG*DG, nullptr, bH, T_*NV, DG, DG, 0);
        gat_scores<<<nb((long)T_*NV*HH, 256), 256>>>(bH, asrc + l*HH*DHD, adst + l*HH*DHD,
                                                     bSS, bSD);
        edge_gather<<<nb((long)T_*NV*32, 256), 256>>>(iROW, iCNT, iSE, ew, bSS, bSD, bH, bX);
        xin = bX;
    }

    // -------- hierarchical fuse (alphas only; z-combine folded into gemm_zx) --------
    fill4<<<nb((long)T_*CC*(DG+1)/4 + 1, 256), 256>>>((float4*)bNUM, ((long)T_*CC*(DG+1)+3)/4);
    fuse_pool<<<nb((long)T_*NV*32, 256), 256>>>(bX, com, nw, bNUM, bCD);
    fuse_finalize<<<T_, 128>>>(bNUM, bCD, bMES, bMAC);
    fuse_alpha<<<nb((long)T_*NV*32, 256), 256>>>(bX, com, bMES, bMAC, bAL);

    // meso rows through Wx[128:256] (interleaved), mac rows through Wx[256:384]
    small_gemm<<<nb((long)T_*CC*1024, 256), 256>>>(
        bMES, bWXI + (long)DG*1024, nullptr, bZME, T_*CC, 1024, DG, DG, 0);
    small_gemm<<<nb((long)T_*1024, 256), 256>>>(
        bMAC, bWXI + (long)2*DG*1024, nullptr, bZME + (long)T_*CC*1024, T_, 1024, DG, DG, 0);

    // -------- LSTM: ZX via reduced pipelined gemm + combine; pipelined fused gates ----
    gemm_zx<<<dim3(8, (T_*NV)/128), 256, GSMEM>>>(bX, bWXI, bBI, bAL, com, bZME, bZX);
    lstm_gate0<<<nb((long)NV*DR, 256), 256>>>(bZX, bHS, bCS);
    float* hcur = bHS;
    float* hnxt = bHS2;
    for (int t = 1; t < T_; t++){
        gemm_lstm<<<dim3((4*DR)/128, NV/128), 256, GSMEM>>>(
            hcur, bWHI, bZX + (long)t*NV*4*DR, hnxt, bCS);
        float* tmp = hcur; hcur = hnxt; hnxt = tmp;
    }

    // -------- decoders (merged first layer: [tanh|sigmoid] split by N-block) --------
    gemm_tf32<<<dim3(2, NV/128), 256, GSMEM>>>(hcur, bWC, bBC, bES1, NV, 2*DD1, DR, 3);
    small_gemm<<<nb((long)NV*DD2, 256), 256>>>(bES1,       eW1, eb1, bEMB, NV, DD2, DD1, 2*DD1, 1);
    small_gemm<<<nb((long)NV*DD2, 256), 256>>>(bES1 + DD1, sW1, sb1, bSC,  NV, DD2, DD1, 2*DD1, 2);

    colnorm_k<<<DD2, 256>>>(bEMB, bCNI);
    norm_sq<<<nb((long)NV*32, 256), 256>>>(bEMB, bCNI, bEMBN, bSQ);

    // -------- adjacency --------
    adj_tc<<<dim3(NV/128, NV/128), 256, adj_smem>>>(bEMBN, bSC, bSQ, out);
}